// round 11
// baseline (speedup 1.0000x reference)
#include <cuda_runtime.h>
#include <cuda_bf16.h>
#include <cstdint>

#define HD   256          // hidden dim
#define BB   256          // batch
#define TT   512          // seq len
#define NP   (BB/2)       // batch pairs = 128
#define NB   128          // persistent grid size (1 CTA/SM, co-resident)
#define NT   256          // threads per CTA

// ---------------------------------------------------------------------------
// Global state (allocation-free scratch)
// Packed-pair layout: [k][pair] float2  (pair p = batches 2p, 2p+1)
// ---------------------------------------------------------------------------
__device__ float2 g_hpk[3][2][HD][NP];      // ping-pong h per layer, 3MB
__device__ float2 g_x[TT][NP];              // transposed packed input, 512KB
__device__ float2 g_hist[TT][HD][NP];       // h3 history, 134MB
__device__ int               g_bar_count;
__device__ volatile unsigned g_bar_gen;

// ---------------------------------------------------------------------------
// Packed f32x2 (Blackwell FFMA2 via PTX only)
// ---------------------------------------------------------------------------
#define FMA2(acc, a, b) asm("fma.rn.f32x2 %0, %1, %2, %0;" : "+l"(acc) : "l"(a), "l"(b))
__device__ __forceinline__ unsigned long long splat2(float w) {
    unsigned long long r; asm("mov.b64 %0, {%1, %1};" : "=l"(r) : "f"(w)); return r;
}
__device__ __forceinline__ float2 unpack2(unsigned long long v) {
    float2 r; asm("mov.b64 {%0, %1}, %2;" : "=f"(r.x), "=f"(r.y) : "l"(v)); return r;
}
__device__ __forceinline__ float sigf(float x) { return 1.f / (1.f + __expf(-x)); }

// ---------------------------------------------------------------------------
// SMEM layout (~192.5 KB dynamic)
// ---------------------------------------------------------------------------
struct Smem {
    float  w[5][HD * 32];        // 5 weight slices [k][32 rows], 160KB
    float2 act[2][64 * 32];      // double-buffered act chunk [k_local][32 pairs], 32KB
    float  w1ih[32];             // layer-1 input column
    float  bias[3][32];          // fused b_ih + b_hh per row
};
#define SMEM_BYTES (sizeof(Smem))

// ---------------------------------------------------------------------------
// Grid barrier (sense via monotonically increasing generation)
// ---------------------------------------------------------------------------
__device__ __forceinline__ void grid_sync(unsigned target) {
    __syncthreads();
    if (threadIdx.x == 0) {
        __threadfence();
        if (atomicAdd(&g_bar_count, 1) == NB - 1) {
            g_bar_count = 0;
            __threadfence();
            g_bar_gen = target;
        } else {
            while (g_bar_gen < target) { }
            __threadfence();
        }
    }
    __syncthreads();
}

// ---------------------------------------------------------------------------
// acc[p] += sum_k W[k][r] * act_pair[k][gp + pg*4 + p],  k = 0..255
// 4 chunks of 64 k, double-buffered SMEM staging with LDG.cg prefetch.
// Warp = 32 rows (lane r), all lanes share pair-group pg.
// ---------------------------------------------------------------------------
__device__ __forceinline__ void accum_mat(
    unsigned long long acc[4],
    const float2* __restrict__ gact,   // [256][128] activation slice base
    const float*  __restrict__ sw,     // [256][32] weight slice
    float2* sbuf,                      // [2][64*32]
    int gp, int r, int pg, int tid)
{
    const int kl = tid >> 2;          // 0..63 : k within chunk
    const int q  = tid & 3;           // quarter of the 32-pair row

    // stage chunk 0
    {
        const float4* s0 = (const float4*)(gact + (size_t)kl * NP + gp) + q * 4;
        float4 p0 = __ldcg(s0 + 0), p1 = __ldcg(s0 + 1),
               p2 = __ldcg(s0 + 2), p3 = __ldcg(s0 + 3);
        float4* d0 = (float4*)(sbuf + (size_t)kl * 32) + q * 4;
        d0[0] = p0; d0[1] = p1; d0[2] = p2; d0[3] = p3;
    }
    __syncthreads();

    #pragma unroll
    for (int c = 0; c < 4; c++) {
        float4 n0, n1, n2, n3;
        if (c < 3) {
            const float4* sn = (const float4*)(gact + ((size_t)(c + 1) * 64 + kl) * NP + gp) + q * 4;
            n0 = __ldcg(sn + 0); n1 = __ldcg(sn + 1);
            n2 = __ldcg(sn + 2); n3 = __ldcg(sn + 3);
        }
        const float2* ab = sbuf + (size_t)(c & 1) * (64 * 32);
        const float*  wk = sw + c * 64 * 32;
        #pragma unroll 8
        for (int k = 0; k < 64; k++) {
            unsigned long long ws = splat2(wk[k * 32 + r]);
            const ulonglong2* ap = (const ulonglong2*)(ab + k * 32 + pg * 4);
            ulonglong2 u0 = ap[0], u1 = ap[1];
            FMA2(acc[0], ws, u0.x);
            FMA2(acc[1], ws, u0.y);
            FMA2(acc[2], ws, u1.x);
            FMA2(acc[3], ws, u1.y);
        }
        if (c < 3) {
            float4* dn = (float4*)(sbuf + (size_t)((c + 1) & 1) * (64 * 32) + (size_t)kl * 32) + q * 4;
            dn[0] = n0; dn[1] = n1; dn[2] = n2; dn[3] = n3;
            __syncthreads();
        }
    }
}

// ---------------------------------------------------------------------------
// LSTM pointwise: gather 4 gates via warp shuffle (row r = g*8+jj), update
// register-resident c, write h pairs to global (and optionally hist).
// ---------------------------------------------------------------------------
__device__ __forceinline__ void pointwise(
    unsigned long long acc[4], float2 cst[4],
    const float* sbias, float2* hdst, float2* histdst,
    int r, int pg, int gp, int ut)
{
    const int jj = r & 7;
    unsigned long long af[4], ag[4], ao[4];
    #pragma unroll
    for (int p = 0; p < 4; p++) {
        af[p] = __shfl_sync(0xFFFFFFFFu, acc[p], jj + 8);
        ag[p] = __shfl_sync(0xFFFFFFFFu, acc[p], jj + 16);
        ao[p] = __shfl_sync(0xFFFFFFFFu, acc[p], jj + 24);
    }
    if (r < 8) {
        const float bi = sbias[r], bf = sbias[8 + r], bg = sbias[16 + r], bo = sbias[24 + r];
        float2 h[4];
        #pragma unroll
        for (int p = 0; p < 4; p++) {
            float2 vi = unpack2(acc[p]), vf = unpack2(af[p]);
            float2 vg = unpack2(ag[p]), vo = unpack2(ao[p]);
            {   // batch 2p
                float I = sigf(vi.x + bi), F = sigf(vf.x + bf);
                float G = tanhf(vg.x + bg), O = sigf(vo.x + bo);
                float cn = F * cst[p].x + I * G;
                cst[p].x = cn; h[p].x = O * tanhf(cn);
            }
            {   // batch 2p+1
                float I = sigf(vi.y + bi), F = sigf(vf.y + bf);
                float G = tanhf(vg.y + bg), O = sigf(vo.y + bo);
                float cn = F * cst[p].y + I * G;
                cst[p].y = cn; h[p].y = O * tanhf(cn);
            }
        }
        float2* d = hdst + (size_t)(ut * 8 + r) * NP + gp + pg * 4;
        ((float4*)d)[0] = make_float4(h[0].x, h[0].y, h[1].x, h[1].y);
        ((float4*)d)[1] = make_float4(h[2].x, h[2].y, h[3].x, h[3].y);
        if (histdst) {
            float2* hd = histdst + (size_t)(ut * 8 + r) * NP + gp + pg * 4;
            ((float4*)hd)[0] = make_float4(h[0].x, h[0].y, h[1].x, h[1].y);
            ((float4*)hd)[1] = make_float4(h[2].x, h[2].y, h[3].x, h[3].y);
        }
    }
}

// ---------------------------------------------------------------------------
// Persistent kernel: 128 CTAs = 4 batch-tiles x 32 unit-tiles.
// Super-step s: L1@t=s, L2@t=s-1, L3@t=s-2, then grid barrier.
// ---------------------------------------------------------------------------
__global__ void __launch_bounds__(NT, 1)
lstm_persistent(const float* __restrict__ W_ih1, const float* __restrict__ W_hh1,
                const float* __restrict__ b_ih1, const float* __restrict__ b_hh1,
                const float* __restrict__ W_ih2, const float* __restrict__ W_hh2,
                const float* __restrict__ b_ih2, const float* __restrict__ b_hh2,
                const float* __restrict__ W_ih3, const float* __restrict__ W_hh3,
                const float* __restrict__ b_ih3, const float* __restrict__ b_hh3)
{
    extern __shared__ __align__(16) unsigned char smem_raw[];
    Smem* sm = (Smem*)smem_raw;

    const int tid = threadIdx.x;
    const int r   = tid & 31;              // row lane: gate g = r>>3, unit jj = r&7
    const int pg  = tid >> 5;              // pair group 0..7 (4 pairs each)
    const int bt  = blockIdx.x & 3;        // batch tile
    const int ut  = blockIdx.x >> 2;       // unit tile (8 hidden units)
    const int gp  = bt * 32;               // global pair base
    const int grow = ((r >> 3) << 8) + (ut << 3) + (r & 7);  // global gate row

    // ---- stage weights (once, reused 512 steps) ----
    const float* wsrc[5] = { W_hh1, W_ih2, W_hh2, W_ih3, W_hh3 };
    #pragma unroll
    for (int m = 0; m < 5; m++) {
        const float* src = wsrc[m] + (size_t)grow * HD;
        for (int k = tid >> 5; k < HD; k += 8)
            sm->w[m][k * 32 + r] = src[k];
    }
    if (tid < 32) {
        sm->w1ih[r]    = W_ih1[grow];
        sm->bias[0][r] = b_ih1[grow] + b_hh1[grow];
        sm->bias[1][r] = b_ih2[grow] + b_hh2[grow];
        sm->bias[2][r] = b_ih3[grow] + b_hh3[grow];
    }
    __syncthreads();

    // register-resident cell state
    float2 c1[4], c2[4], c3[4];
    #pragma unroll
    for (int p = 0; p < 4; p++) {
        c1[p] = make_float2(0.f, 0.f);
        c2[p] = make_float2(0.f, 0.f);
        c3[p] = make_float2(0.f, 0.f);
    }

    for (int s = 0; s < TT + 2; s++) {
        const int rp = (s + 1) & 1;        // read parity ( = (s-1)&1 )
        const int wp = s & 1;              // write parity

        // ---- layer 1 @ t = s ----
        if (s < TT) {
            unsigned long long acc[4] = {0ull, 0ull, 0ull, 0ull};
            unsigned long long ws1 = splat2(sm->w1ih[r]);
            const ulonglong2* xp = (const ulonglong2*)(&g_x[s][gp + pg * 4]);
            ulonglong2 x0 = xp[0], x1 = xp[1];
            FMA2(acc[0], ws1, x0.x); FMA2(acc[1], ws1, x0.y);
            FMA2(acc[2], ws1, x1.x); FMA2(acc[3], ws1, x1.y);
            accum_mat(acc, &g_hpk[0][rp][0][0], sm->w[0], &sm->act[0][0], gp, r, pg, tid);
            pointwise(acc, c1, sm->bias[0], &g_hpk[0][wp][0][0], nullptr, r, pg, gp, ut);
        }
        // ---- layer 2 @ t = s-1 ----
        if (s >= 1 && s <= TT) {
            unsigned long long acc[4] = {0ull, 0ull, 0ull, 0ull};
            accum_mat(acc, &g_hpk[0][rp][0][0], sm->w[1], &sm->act[0][0], gp, r, pg, tid);
            accum_mat(acc, &g_hpk[1][rp][0][0], sm->w[2], &sm->act[0][0], gp, r, pg, tid);
            pointwise(acc, c2, sm->bias[1], &g_hpk[1][wp][0][0], nullptr, r, pg, gp, ut);
        }
        // ---- layer 3 @ t = s-2 (also record hist) ----
        if (s >= 2) {
            unsigned long long acc[4] = {0ull, 0ull, 0ull, 0ull};
            accum_mat(acc, &g_hpk[1][rp][0][0], sm->w[3], &sm->act[0][0], gp, r, pg, tid);
            accum_mat(acc, &g_hpk[2][rp][0][0], sm->w[4], &sm->act[0][0], gp, r, pg, tid);
            pointwise(acc, c3, sm->bias[2], &g_hpk[2][wp][0][0], &g_hist[s - 2][0][0],
                      r, pg, gp, ut);
        }
        grid_sync((unsigned)(s + 1));
    }
}

// ---------------------------------------------------------------------------
// Init: zero h buffers, reset barrier, build packed-transposed input
// ---------------------------------------------------------------------------
__global__ void init_state(const float* __restrict__ input)
{
    const int idx = blockIdx.x * blockDim.x + threadIdx.x;
    const int stride = gridDim.x * blockDim.x;
    if (idx == 0) { g_bar_count = 0; g_bar_gen = 0; }
    float2* hz = &g_hpk[0][0][0][0];
    for (int i = idx; i < 3 * 2 * HD * NP; i += stride)
        hz[i] = make_float2(0.f, 0.f);
    for (int i = idx; i < TT * NP; i += stride) {
        int t = i >> 7, p = i & (NP - 1);
        ((float2*)g_x)[i] = make_float2(input[(size_t)(2 * p) * TT + t],
                                        input[(size_t)(2 * p + 1) * TT + t]);
    }
}

// ---------------------------------------------------------------------------
// Output head: out[b,t] = dot(h3[t,b,:], W_lin) + b_lin
// block = t, thread = b; hist float layout [t][k][b] is coalesced over b.
// ---------------------------------------------------------------------------
__global__ void __launch_bounds__(256)
linear_head(const float* __restrict__ W_lin, const float* __restrict__ b_lin,
            float* __restrict__ out)
{
    __shared__ float sw[HD];
    const int t = blockIdx.x, b = threadIdx.x;
    sw[b] = W_lin[b];
    __syncthreads();
    const float* hp = (const float*)&g_hist[t][0][0];
    float s = 0.f;
    #pragma unroll 8
    for (int k = 0; k < HD; k++)
        s += hp[(size_t)k * BB + b] * sw[k];
    out[(size_t)b * TT + t] = s + b_lin[0];
}

// ---------------------------------------------------------------------------
// 3 graph nodes total: init -> persistent -> head
// ---------------------------------------------------------------------------
extern "C" void kernel_launch(void* const* d_in, const int* in_sizes, int n_in,
                              void* d_out, int out_size)
{
    const float* input = (const float*)d_in[0];
    const float* W_ih1 = (const float*)d_in[1];
    const float* W_hh1 = (const float*)d_in[2];
    const float* b_ih1 = (const float*)d_in[3];
    const float* b_hh1 = (const float*)d_in[4];
    const float* W_ih2 = (const float*)d_in[5];
    const float* W_hh2 = (const float*)d_in[6];
    const float* b_ih2 = (const float*)d_in[7];
    const float* b_hh2 = (const float*)d_in[8];
    const float* W_ih3 = (const float*)d_in[9];
    const float* W_hh3 = (const float*)d_in[10];
    const float* b_ih3 = (const float*)d_in[11];
    const float* b_hh3 = (const float*)d_in[12];
    const float* W_lin = (const float*)d_in[13];
    const float* b_lin = (const float*)d_in[14];
    float* out = (float*)d_out;

    cudaFuncSetAttribute(lstm_persistent,
                         cudaFuncAttributeMaxDynamicSharedMemorySize, (int)SMEM_BYTES);

    init_state<<<256, 256>>>(input);
    lstm_persistent<<<NB, NT, SMEM_BYTES>>>(W_ih1, W_hh1, b_ih1, b_hh1,
                                            W_ih2, W_hh2, b_ih2, b_hh2,
                                            W_ih3, W_hh3, b_ih3, b_hh3);
    linear_head<<<TT, 256>>>(W_lin, b_lin, out);
}

// round 12
// speedup vs baseline: 1.0010x; 1.0010x over previous
#include <cuda_runtime.h>
#include <cuda_bf16.h>
#include <cstdint>

#define HD   256          // hidden dim
#define BB   256          // batch
#define TT   512          // seq len
#define NP   (BB/2)       // batch pairs = 128
#define NB   128          // persistent grid size (1 CTA/SM, co-resident)
#define NT   256          // threads per CTA

// ---------------------------------------------------------------------------
// Global state (allocation-free scratch)
// Packed-pair layout: [k][pair] float2  (pair p = batches 2p, 2p+1)
// ---------------------------------------------------------------------------
__device__ float2 g_hpk[3][2][HD][NP];      // ping-pong h per layer, 3MB
__device__ float2 g_x[TT][NP];              // transposed packed input, 512KB
__device__ float2 g_hist[TT][HD][NP];       // h3 history, 134MB
__device__ int               g_bar_count;
__device__ volatile unsigned g_bar_gen;

// ---------------------------------------------------------------------------
// Packed f32x2 (Blackwell FFMA2 via PTX only)
// ---------------------------------------------------------------------------
#define FMA2(acc, a, b) asm("fma.rn.f32x2 %0, %1, %2, %0;" : "+l"(acc) : "l"(a), "l"(b))
__device__ __forceinline__ unsigned long long splat2(float w) {
    unsigned long long r; asm("mov.b64 %0, {%1, %1};" : "=l"(r) : "f"(w)); return r;
}
__device__ __forceinline__ float2 unpack2(unsigned long long v) {
    float2 r; asm("mov.b64 {%0, %1}, %2;" : "=f"(r.x), "=f"(r.y) : "l"(v)); return r;
}
__device__ __forceinline__ float sigf(float x) { return 1.f / (1.f + __expf(-x)); }

// ---------------------------------------------------------------------------
// SMEM layout (~192.5 KB dynamic)
// ---------------------------------------------------------------------------
struct Smem {
    float  w[5][HD * 32];        // 5 weight slices [k][32 rows], 160KB
    float2 act[2][64 * 32];      // double-buffered act chunk [k_local][32 pairs], 32KB
    float  w1ih[32];             // layer-1 input column
    float  bias[3][32];          // fused b_ih + b_hh per row
};
#define SMEM_BYTES (sizeof(Smem))

// ---------------------------------------------------------------------------
// Grid barrier (sense via monotonically increasing generation)
// ---------------------------------------------------------------------------
__device__ __forceinline__ void grid_sync(unsigned target) {
    __syncthreads();
    if (threadIdx.x == 0) {
        __threadfence();
        if (atomicAdd(&g_bar_count, 1) == NB - 1) {
            g_bar_count = 0;
            __threadfence();
            g_bar_gen = target;
        } else {
            while (g_bar_gen < target) { }
            __threadfence();
        }
    }
    __syncthreads();
}

// ---------------------------------------------------------------------------
// acc[p] += sum_k W[k][r] * act_pair[k][gp + pg*4 + p],  k = 0..255
// 4 chunks of 64 k, double-buffered SMEM staging with LDG.cg prefetch.
// Warp = 32 rows (lane r), all lanes share pair-group pg.
// ---------------------------------------------------------------------------
__device__ __forceinline__ void accum_mat(
    unsigned long long acc[4],
    const float2* __restrict__ gact,   // [256][128] activation slice base
    const float*  __restrict__ sw,     // [256][32] weight slice
    float2* sbuf,                      // [2][64*32]
    int gp, int r, int pg, int tid)
{
    const int kl = tid >> 2;          // 0..63 : k within chunk
    const int q  = tid & 3;           // quarter of the 32-pair row

    // stage chunk 0
    {
        const float4* s0 = (const float4*)(gact + (size_t)kl * NP + gp) + q * 4;
        float4 p0 = __ldcg(s0 + 0), p1 = __ldcg(s0 + 1),
               p2 = __ldcg(s0 + 2), p3 = __ldcg(s0 + 3);
        float4* d0 = (float4*)(sbuf + (size_t)kl * 32) + q * 4;
        d0[0] = p0; d0[1] = p1; d0[2] = p2; d0[3] = p3;
    }
    __syncthreads();

    #pragma unroll
    for (int c = 0; c < 4; c++) {
        float4 n0, n1, n2, n3;
        if (c < 3) {
            const float4* sn = (const float4*)(gact + ((size_t)(c + 1) * 64 + kl) * NP + gp) + q * 4;
            n0 = __ldcg(sn + 0); n1 = __ldcg(sn + 1);
            n2 = __ldcg(sn + 2); n3 = __ldcg(sn + 3);
        }
        const float2* ab = sbuf + (size_t)(c & 1) * (64 * 32);
        const float*  wk = sw + c * 64 * 32;
        #pragma unroll 8
        for (int k = 0; k < 64; k++) {
            unsigned long long ws = splat2(wk[k * 32 + r]);
            const ulonglong2* ap = (const ulonglong2*)(ab + k * 32 + pg * 4);
            ulonglong2 u0 = ap[0], u1 = ap[1];
            FMA2(acc[0], ws, u0.x);
            FMA2(acc[1], ws, u0.y);
            FMA2(acc[2], ws, u1.x);
            FMA2(acc[3], ws, u1.y);
        }
        if (c < 3) {
            float4* dn = (float4*)(sbuf + (size_t)((c + 1) & 1) * (64 * 32) + (size_t)kl * 32) + q * 4;
            dn[0] = n0; dn[1] = n1; dn[2] = n2; dn[3] = n3;
            __syncthreads();
        }
    }
}

// ---------------------------------------------------------------------------
// LSTM pointwise: gather 4 gates via warp shuffle (row r = g*8+jj), update
// register-resident c, write h pairs to global (and optionally hist).
// ---------------------------------------------------------------------------
__device__ __forceinline__ void pointwise(
    unsigned long long acc[4], float2 cst[4],
    const float* sbias, float2* hdst, float2* histdst,
    int r, int pg, int gp, int ut)
{
    const int jj = r & 7;
    unsigned long long af[4], ag[4], ao[4];
    #pragma unroll
    for (int p = 0; p < 4; p++) {
        af[p] = __shfl_sync(0xFFFFFFFFu, acc[p], jj + 8);
        ag[p] = __shfl_sync(0xFFFFFFFFu, acc[p], jj + 16);
        ao[p] = __shfl_sync(0xFFFFFFFFu, acc[p], jj + 24);
    }
    if (r < 8) {
        const float bi = sbias[r], bf = sbias[8 + r], bg = sbias[16 + r], bo = sbias[24 + r];
        float2 h[4];
        #pragma unroll
        for (int p = 0; p < 4; p++) {
            float2 vi = unpack2(acc[p]), vf = unpack2(af[p]);
            float2 vg = unpack2(ag[p]), vo = unpack2(ao[p]);
            {   // batch 2p
                float I = sigf(vi.x + bi), F = sigf(vf.x + bf);
                float G = tanhf(vg.x + bg), O = sigf(vo.x + bo);
                float cn = F * cst[p].x + I * G;
                cst[p].x = cn; h[p].x = O * tanhf(cn);
            }
            {   // batch 2p+1
                float I = sigf(vi.y + bi), F = sigf(vf.y + bf);
                float G = tanhf(vg.y + bg), O = sigf(vo.y + bo);
                float cn = F * cst[p].y + I * G;
                cst[p].y = cn; h[p].y = O * tanhf(cn);
            }
        }
        float2* d = hdst + (size_t)(ut * 8 + r) * NP + gp + pg * 4;
        ((float4*)d)[0] = make_float4(h[0].x, h[0].y, h[1].x, h[1].y);
        ((float4*)d)[1] = make_float4(h[2].x, h[2].y, h[3].x, h[3].y);
        if (histdst) {
            float2* hd = histdst + (size_t)(ut * 8 + r) * NP + gp + pg * 4;
            ((float4*)hd)[0] = make_float4(h[0].x, h[0].y, h[1].x, h[1].y);
            ((float4*)hd)[1] = make_float4(h[2].x, h[2].y, h[3].x, h[3].y);
        }
    }
}

// ---------------------------------------------------------------------------
// Persistent kernel: 128 CTAs = 4 batch-tiles x 32 unit-tiles.
// Super-step s: L1@t=s, L2@t=s-1, L3@t=s-2, then grid barrier.
// ---------------------------------------------------------------------------
__global__ void __launch_bounds__(NT, 1)
lstm_persistent(const float* __restrict__ W_ih1, const float* __restrict__ W_hh1,
                const float* __restrict__ b_ih1, const float* __restrict__ b_hh1,
                const float* __restrict__ W_ih2, const float* __restrict__ W_hh2,
                const float* __restrict__ b_ih2, const float* __restrict__ b_hh2,
                const float* __restrict__ W_ih3, const float* __restrict__ W_hh3,
                const float* __restrict__ b_ih3, const float* __restrict__ b_hh3)
{
    extern __shared__ __align__(16) unsigned char smem_raw[];
    Smem* sm = (Smem*)smem_raw;

    const int tid = threadIdx.x;
    const int r   = tid & 31;              // row lane: gate g = r>>3, unit jj = r&7
    const int pg  = tid >> 5;              // pair group 0..7 (4 pairs each)
    const int bt  = blockIdx.x & 3;        // batch tile
    const int ut  = blockIdx.x >> 2;       // unit tile (8 hidden units)
    const int gp  = bt * 32;               // global pair base
    const int grow = ((r >> 3) << 8) + (ut << 3) + (r & 7);  // global gate row

    // ---- stage weights (once, reused 512 steps) ----
    const float* wsrc[5] = { W_hh1, W_ih2, W_hh2, W_ih3, W_hh3 };
    #pragma unroll
    for (int m = 0; m < 5; m++) {
        const float* src = wsrc[m] + (size_t)grow * HD;
        for (int k = tid >> 5; k < HD; k += 8)
            sm->w[m][k * 32 + r] = src[k];
    }
    if (tid < 32) {
        sm->w1ih[r]    = W_ih1[grow];
        sm->bias[0][r] = b_ih1[grow] + b_hh1[grow];
        sm->bias[1][r] = b_ih2[grow] + b_hh2[grow];
        sm->bias[2][r] = b_ih3[grow] + b_hh3[grow];
    }
    __syncthreads();

    // register-resident cell state
    float2 c1[4], c2[4], c3[4];
    #pragma unroll
    for (int p = 0; p < 4; p++) {
        c1[p] = make_float2(0.f, 0.f);
        c2[p] = make_float2(0.f, 0.f);
        c3[p] = make_float2(0.f, 0.f);
    }

    for (int s = 0; s < TT + 2; s++) {
        const int rp = (s + 1) & 1;        // read parity ( = (s-1)&1 )
        const int wp = s & 1;              // write parity

        // ---- layer 1 @ t = s ----
        if (s < TT) {
            unsigned long long acc[4] = {0ull, 0ull, 0ull, 0ull};
            unsigned long long ws1 = splat2(sm->w1ih[r]);
            const ulonglong2* xp = (const ulonglong2*)(&g_x[s][gp + pg * 4]);
            ulonglong2 x0 = xp[0], x1 = xp[1];
            FMA2(acc[0], ws1, x0.x); FMA2(acc[1], ws1, x0.y);
            FMA2(acc[2], ws1, x1.x); FMA2(acc[3], ws1, x1.y);
            accum_mat(acc, &g_hpk[0][rp][0][0], sm->w[0], &sm->act[0][0], gp, r, pg, tid);
            pointwise(acc, c1, sm->bias[0], &g_hpk[0][wp][0][0], nullptr, r, pg, gp, ut);
        }
        // ---- layer 2 @ t = s-1 ----
        if (s >= 1 && s <= TT) {
            unsigned long long acc[4] = {0ull, 0ull, 0ull, 0ull};
            accum_mat(acc, &g_hpk[0][rp][0][0], sm->w[1], &sm->act[0][0], gp, r, pg, tid);
            accum_mat(acc, &g_hpk[1][rp][0][0], sm->w[2], &sm->act[0][0], gp, r, pg, tid);
            pointwise(acc, c2, sm->bias[1], &g_hpk[1][wp][0][0], nullptr, r, pg, gp, ut);
        }
        // ---- layer 3 @ t = s-2 (also record hist) ----
        if (s >= 2) {
            unsigned long long acc[4] = {0ull, 0ull, 0ull, 0ull};
            accum_mat(acc, &g_hpk[1][rp][0][0], sm->w[3], &sm->act[0][0], gp, r, pg, tid);
            accum_mat(acc, &g_hpk[2][rp][0][0], sm->w[4], &sm->act[0][0], gp, r, pg, tid);
            pointwise(acc, c3, sm->bias[2], &g_hpk[2][wp][0][0], &g_hist[s - 2][0][0],
                      r, pg, gp, ut);
        }
        grid_sync((unsigned)(s + 1));
    }
}

// ---------------------------------------------------------------------------
// Init: zero h buffers, reset barrier, build packed-transposed input
// ---------------------------------------------------------------------------
__global__ void init_state(const float* __restrict__ input)
{
    const int idx = blockIdx.x * blockDim.x + threadIdx.x;
    const int stride = gridDim.x * blockDim.x;
    if (idx == 0) { g_bar_count = 0; g_bar_gen = 0; }
    float2* hz = &g_hpk[0][0][0][0];
    for (int i = idx; i < 3 * 2 * HD * NP; i += stride)
        hz[i] = make_float2(0.f, 0.f);
    for (int i = idx; i < TT * NP; i += stride) {
        int t = i >> 7, p = i & (NP - 1);
        ((float2*)g_x)[i] = make_float2(input[(size_t)(2 * p) * TT + t],
                                        input[(size_t)(2 * p + 1) * TT + t]);
    }
}

// ---------------------------------------------------------------------------
// Output head: out[b,t] = dot(h3[t,b,:], W_lin) + b_lin
// block = t, thread = b; hist float layout [t][k][b] is coalesced over b.
// ---------------------------------------------------------------------------
__global__ void __launch_bounds__(256)
linear_head(const float* __restrict__ W_lin, const float* __restrict__ b_lin,
            float* __restrict__ out)
{
    __shared__ float sw[HD];
    const int t = blockIdx.x, b = threadIdx.x;
    sw[b] = W_lin[b];
    __syncthreads();
    const float* hp = (const float*)&g_hist[t][0][0];
    float s = 0.f;
    #pragma unroll 8
    for (int k = 0; k < HD; k++)
        s += hp[(size_t)k * BB + b] * sw[k];
    out[(size_t)b * TT + t] = s + b_lin[0];
}

// ---------------------------------------------------------------------------
// 3 graph nodes total: init -> persistent -> head
// ---------------------------------------------------------------------------
extern "C" void kernel_launch(void* const* d_in, const int* in_sizes, int n_in,
                              void* d_out, int out_size)
{
    const float* input = (const float*)d_in[0];
    const float* W_ih1 = (const float*)d_in[1];
    const float* W_hh1 = (const float*)d_in[2];
    const float* b_ih1 = (const float*)d_in[3];
    const float* b_hh1 = (const float*)d_in[4];
    const float* W_ih2 = (const float*)d_in[5];
    const float* W_hh2 = (const float*)d_in[6];
    const float* b_ih2 = (const float*)d_in[7];
    const float* b_hh2 = (const float*)d_in[8];
    const float* W_ih3 = (const float*)d_in[9];
    const float* W_hh3 = (const float*)d_in[10];
    const float* b_ih3 = (const float*)d_in[11];
    const float* b_hh3 = (const float*)d_in[12];
    const float* W_lin = (const float*)d_in[13];
    const float* b_lin = (const float*)d_in[14];
    float* out = (float*)d_out;

    cudaFuncSetAttribute(lstm_persistent,
                         cudaFuncAttributeMaxDynamicSharedMemorySize, (int)SMEM_BYTES);

    init_state<<<256, 256>>>(input);
    lstm_persistent<<<NB, NT, SMEM_BYTES>>>(W_ih1, W_hh1, b_ih1, b_hh1,
                                            W_ih2, W_hh2, b_ih2, b_hh2,
                                            W_ih3, W_hh3, b_ih3, b_hh3);
    linear_head<<<TT, 256>>>(W_lin, b_lin, out);
}

// round 14
// speedup vs baseline: 2.7618x; 2.7590x over previous
#include <cuda_runtime.h>
#include <cuda_bf16.h>
#include <cstdint>

#define HD 256
#define BB 256
#define TT 512
#define NB 96
#define NT 128

// ---- dynamic SMEM offsets (base manually 1024-aligned) ----
#define SM_BIAS  64           // 128 f32
#define SM_W1    640          // 128 f32
#define SM_STAGE 2048         // 2 bufs x 48KB
#define OFF_WHI  0
#define OFF_WLO  16384
#define OFF_AHI  32768
#define OFF_ALO  40960
#define BUF_SZ   49152
#define SM_D     (SM_STAGE + 2 * BUF_SZ)       // 128 x 68 f32 = 34816
#define SM_H     (SM_D + 34816)                // 64 x 33 f32 = 8448
#define SM_BYTES (SM_H + 8448 + 1024)

// ---------------------------------------------------------------------------
// Global scratch (allocation-free)
// ---------------------------------------------------------------------------
__device__ __align__(16) __nv_bfloat16 g_wb[2][5][8][4 * 8192];    // swizzled W images (hi/lo)
__device__ __align__(16) __nv_bfloat16 g_ab[3][2][2][4][4 * 4096]; // swizzled act images
__device__ float g_x[TT][BB];
__device__ float g_hist[TT][HD][BB];
__device__ int               g_bar_count;
__device__ volatile unsigned g_bar_gen;

// ---------------------------------------------------------------------------
// PTX helpers (all sm_80+ base features — legal on compute_103)
// ---------------------------------------------------------------------------
__device__ __forceinline__ uint32_t s2u(const void* p) {
    uint32_t a;
    asm("{ .reg .u64 t; cvta.to.shared.u64 t, %1; cvt.u32.u64 %0, t; }" : "=r"(a) : "l"(p));
    return a;
}
#define CPA(dst, src) \
    asm volatile("cp.async.cg.shared.global [%0], [%1], 16;" \
        :: "r"(dst), "l"(__cvta_generic_to_global(src)))
#define CPC()  asm volatile("cp.async.commit_group;" ::: "memory")
#define CPW0() asm volatile("cp.async.wait_group 0;" ::: "memory")

#define LDSM4(r, a) \
    asm volatile("ldmatrix.sync.aligned.m8n8.x4.shared.b16 {%0,%1,%2,%3}, [%4];" \
        : "=r"((r)[0]), "=r"((r)[1]), "=r"((r)[2]), "=r"((r)[3]) : "r"(a))

__device__ __forceinline__ void mma16(float* d, const uint32_t* a, const uint32_t* b) {
    asm volatile("mma.sync.aligned.m16n8k16.row.col.f32.bf16.bf16.f32 "
        "{%0,%1,%2,%3}, {%4,%5,%6,%7}, {%8,%9}, {%0,%1,%2,%3};"
        : "+f"(d[0]), "+f"(d[1]), "+f"(d[2]), "+f"(d[3])
        : "r"(a[0]), "r"(a[1]), "r"(a[2]), "r"(a[3]), "r"(b[0]), "r"(b[1]));
}

__device__ __forceinline__ int swz(int o) { return o ^ ((o >> 3) & 0x70); }
__device__ __forceinline__ float sigf(float x) { return 1.f / (1.f + __expf(-x)); }

__device__ __forceinline__ void grid_sync(unsigned target) {
    __syncthreads();
    if (threadIdx.x == 0) {
        __threadfence();
        if (atomicAdd(&g_bar_count, 1) == NB - 1) {
            g_bar_count = 0;
            __threadfence();
            g_bar_gen = target;
        } else {
            while (g_bar_gen < target) { }
            __threadfence();
        }
    }
    __syncthreads();
}

// ---------------------------------------------------------------------------
// Prep: split fp32 weights to bf16 hi/lo, rows reordered (r = u*4+g), swizzled
// ---------------------------------------------------------------------------
__global__ void prep_weights(const float* __restrict__ A0, const float* __restrict__ A1,
                             const float* __restrict__ A2, const float* __restrict__ A3,
                             const float* __restrict__ A4)
{
    const float* mats[5] = { A0, A1, A2, A3, A4 };
    const int total = 5 * 8 * 128 * 256;
    for (int idx = blockIdx.x * blockDim.x + threadIdx.x; idx < total;
         idx += gridDim.x * blockDim.x) {
        int m  = idx / 262144, rem = idx % 262144;
        int mt = rem >> 15,    r2  = rem & 32767;
        int r  = r2 >> 8,      k   = r2 & 255;
        int orow = (r & 3) * 256 + mt * 32 + (r >> 2);
        float wv = mats[m][orow * HD + k];
        __nv_bfloat16 hi = __float2bfloat16(wv);
        __nv_bfloat16 lo = __float2bfloat16(wv - __bfloat162float(hi));
        int off = r * 128 + (k & 63) * 2;
        int di  = (k >> 6) * 8192 + (swz(off) >> 1);
        g_wb[0][m][mt][di] = hi;
        g_wb[1][m][mt][di] = lo;
    }
}

// ---------------------------------------------------------------------------
// Init: zero act images, reset barrier, transpose input
// ---------------------------------------------------------------------------
__global__ void init_state(const float* __restrict__ input)
{
    const int idx = blockIdx.x * blockDim.x + threadIdx.x;
    const int stride = gridDim.x * blockDim.x;
    if (idx == 0) { g_bar_count = 0; g_bar_gen = 0; }
    uint4* az = (uint4*)&g_ab[0][0][0][0][0];
    const int nz = (int)(sizeof(g_ab) / 16);
    for (int i = idx; i < nz; i += stride) az[i] = make_uint4(0, 0, 0, 0);
    for (int i = idx; i < TT * BB; i += stride) {
        int t = i >> 8, b = i & 255;
        g_x[t][b] = input[(size_t)b * TT + t];
    }
}

// ---------------------------------------------------------------------------
// Stage one K-chunk: W hi/lo 16KB each + act hi/lo 8KB each (24 cp.async/thr)
// ---------------------------------------------------------------------------
__device__ __forceinline__ void stage_chunk(uint32_t bd,
    const __nv_bfloat16* whi, const __nv_bfloat16* wlo,
    const __nv_bfloat16* ahi, const __nv_bfloat16* alo, int tid)
{
    #pragma unroll
    for (int q = 0; q < 8; q++) {
        uint32_t o = (uint32_t)(q * 128 + tid) * 16;
        CPA(bd + OFF_WHI + o, (const char*)whi + o);
        CPA(bd + OFF_WLO + o, (const char*)wlo + o);
    }
    #pragma unroll
    for (int q = 0; q < 4; q++) {
        uint32_t o = (uint32_t)(q * 128 + tid) * 16;
        CPA(bd + OFF_AHI + o, (const char*)ahi + o);
        CPA(bd + OFF_ALO + o, (const char*)alo + o);
    }
}

// ---------------------------------------------------------------------------
// Compute one chunk (K=64): 3 split terms, 2 m-tiles x 8 n-tiles per warp
// ---------------------------------------------------------------------------
__device__ __forceinline__ void compute_chunk(uint32_t bd, float acc[2][8][4],
                                              int a_off0, int b_off0)
{
    const uint32_t whi_b = bd + OFF_WHI, wlo_b = bd + OFF_WLO;
    const uint32_t ahi_b = bd + OFF_AHI, alo_b = bd + OFF_ALO;
    #pragma unroll
    for (int ks = 0; ks < 4; ks++) {
        uint32_t ahh[2][4], alw[2][4];
        #pragma unroll
        for (int mi = 0; mi < 2; mi++) {
            int o = a_off0 + mi * 2048 + ks * 32;
            LDSM4(ahh[mi], whi_b + swz(o));
            LDSM4(alw[mi], wlo_b + swz(o));
        }
        uint32_t bh[4][4], bl[4][4];
        #pragma unroll
        for (int np = 0; np < 4; np++) {
            int o = b_off0 + np * 2048 + ks * 32;
            LDSM4(bh[np], ahi_b + swz(o));
            LDSM4(bl[np], alo_b + swz(o));
        }
        #pragma unroll
        for (int mi = 0; mi < 2; mi++) {
            #pragma unroll
            for (int ni = 0; ni < 8; ni++) {
                const uint32_t* bhp = &bh[ni >> 1][(ni & 1) * 2];
                const uint32_t* blp = &bl[ni >> 1][(ni & 1) * 2];
                mma16(acc[mi][ni], ahh[mi], bhp);   // Whi * ahi
                mma16(acc[mi][ni], ahh[mi], blp);   // Whi * alo
                mma16(acc[mi][ni], alw[mi], bhp);   // Wlo * ahi
            }
        }
    }
}

// ---------------------------------------------------------------------------
// Persistent HMMA LSTM: 96 CTAs = 3 layers x 8 mtiles x 4 ntiles
// ---------------------------------------------------------------------------
__global__ void __launch_bounds__(NT, 1)
lstm_tc(const float* __restrict__ W_ih1,
        const float* __restrict__ b_ih1, const float* __restrict__ b_hh1,
        const float* __restrict__ b_ih2, const float* __restrict__ b_hh2,
        const float* __restrict__ b_ih3, const float* __restrict__ b_hh3)
{
    extern __shared__ __align__(16) unsigned char smraw[];
    char* smp = (char*)(((uintptr_t)smraw + 1023) & ~(uintptr_t)1023);
    const uint32_t sb = s2u(smp);

    const int tid = threadIdx.x;
    const int w   = tid >> 5, l = tid & 31;
    const int layer = blockIdx.x >> 5;
    const int mt = (blockIdx.x & 31) >> 2;
    const int nt = blockIdx.x & 3;

    // fused bias + layer-1 input column (reordered rows)
    {
        const float* bi = (layer == 0) ? b_ih1 : (layer == 1) ? b_ih2 : b_ih3;
        const float* bh = (layer == 0) ? b_hh1 : (layer == 1) ? b_hh2 : b_hh3;
        int orow = (tid & 3) * 256 + mt * 32 + (tid >> 2);
        ((float*)(smp + SM_BIAS))[tid] = bi[orow] + bh[orow];
        ((float*)(smp + SM_W1))[tid]   = (layer == 0) ? W_ih1[orow] : 0.f;
    }
    __syncthreads();

    // ldmatrix lane base offsets
    const int a_off0 = (w * 32 + (l & 7) + ((l >> 3) & 1) * 8) * 128 + ((l >> 4) & 1) * 16;
    const int b_off0 = ((l & 7) + ((l >> 4) & 1) * 8) * 128 + ((l >> 3) & 1) * 16;

    float cst[16];
    #pragma unroll
    for (int i = 0; i < 16; i++) cst[i] = 0.f;

    const int u = tid >> 2, n0 = (tid & 3) * 16;
    float* sD = (float*)(smp + SM_D);
    float* sH = (float*)(smp + SM_H);

    #pragma unroll 1
    for (int s = 0; s < TT + 2; s++) {
        const int rp = (s + 1) & 1, wp = s & 1;
        const int t = s - layer;
        if (t >= 0 && t < TT) {
            const int nm = (layer == 0) ? 1 : 2;
            const int NQ = nm * 4;
            float acc[2][8][4];
            #pragma unroll
            for (int mi = 0; mi < 2; mi++)
                #pragma unroll
                for (int ni = 0; ni < 8; ni++)
                    #pragma unroll
                    for (int e = 0; e < 4; e++) acc[mi][ni][e] = 0.f;

            // chunk q -> (matrix m = q>>2, kchunk kc = q&3)
            auto chunk_ptrs = [&](int q, const __nv_bfloat16*& whi, const __nv_bfloat16*& wlo,
                                  const __nv_bfloat16*& ahi, const __nv_bfloat16*& alo) {
                int m = q >> 2, kc = q & 3;
                int mi_, srcL;
                if (layer == 0)      { mi_ = 0;          srcL = 0; }
                else if (layer == 1) { mi_ = m ? 2 : 1;  srcL = m ? 1 : 0; }
                else                 { mi_ = m ? 4 : 3;  srcL = m ? 2 : 1; }
                whi = &g_wb[0][mi_][mt][kc * 8192];
                wlo = &g_wb[1][mi_][mt][kc * 8192];
                ahi = &g_ab[srcL][rp][0][nt][kc * 4096];
                alo = &g_ab[srcL][rp][1][nt][kc * 4096];
            };

            {   // prologue: stage chunk 0
                const __nv_bfloat16 *whi, *wlo, *ahi, *alo;
                chunk_ptrs(0, whi, wlo, ahi, alo);
                stage_chunk(sb + SM_STAGE, whi, wlo, ahi, alo, tid);
                CPC();
            }
            #pragma unroll 1
            for (int q = 0; q < NQ; q++) {
                CPW0();
                __syncthreads();
                if (q + 1 < NQ) {
                    const __nv_bfloat16 *whi, *wlo, *ahi, *alo;
                    chunk_ptrs(q + 1, whi, wlo, ahi, alo);
                    stage_chunk(sb + SM_STAGE + ((q + 1) & 1) * BUF_SZ, whi, wlo, ahi, alo, tid);
                    CPC();
                }
                compute_chunk(sb + SM_STAGE + (q & 1) * BUF_SZ, acc, a_off0, b_off0);
            }

            // ---- store D frags to SMEM [128][68] ----
            {
                const int row0 = w * 32 + (l >> 2);
                const int colb = (l & 3) * 2;
                #pragma unroll
                for (int mi = 0; mi < 2; mi++)
                    #pragma unroll
                    for (int ni = 0; ni < 8; ni++) {
                        float2* p0 = (float2*)&sD[(row0 + mi * 16) * 68 + ni * 8 + colb];
                        float2* p1 = (float2*)&sD[(row0 + mi * 16 + 8) * 68 + ni * 8 + colb];
                        *p0 = make_float2(acc[mi][ni][0], acc[mi][ni][1]);
                        *p1 = make_float2(acc[mi][ni][2], acc[mi][ni][3]);
                    }
            }
            __syncthreads();

            // ---- pointwise LSTM cell ----
            {
                const float* q0 = &sD[(4 * u + 0) * 68 + n0];
                const float* q1 = &sD[(4 * u + 1) * 68 + n0];
                const float* q2 = &sD[(4 * u + 2) * 68 + n0];
                const float* q3 = &sD[(4 * u + 3) * 68 + n0];
                const float b0 = ((float*)(smp + SM_BIAS))[4 * u + 0];
                const float b1 = ((float*)(smp + SM_BIAS))[4 * u + 1];
                const float b2 = ((float*)(smp + SM_BIAS))[4 * u + 2];
                const float b3 = ((float*)(smp + SM_BIAS))[4 * u + 3];
                float w0 = 0.f, w1 = 0.f, w2 = 0.f, w3 = 0.f;
                if (layer == 0) {
                    w0 = ((float*)(smp + SM_W1))[4 * u + 0];
                    w1 = ((float*)(smp + SM_W1))[4 * u + 1];
                    w2 = ((float*)(smp + SM_W1))[4 * u + 2];
                    w3 = ((float*)(smp + SM_W1))[4 * u + 3];
                }
                const int nb = nt * 64 + n0;
                float hloc[16];
                #pragma unroll
                for (int i = 0; i < 16; i++) {
                    float gi = q0[i] + b0, gf = q1[i] + b1;
                    float gg = q2[i] + b2, go = q3[i] + b3;
                    if (layer == 0) {
                        float xv = g_x[t][nb + i];
                        gi += w0 * xv; gf += w1 * xv; gg += w2 * xv; go += w3 * xv;
                    }
                    float I = sigf(gi), F = sigf(gf), G = tanhf(gg), O = sigf(go);
                    float cn = F * cst[i] + I * G;
                    cst[i] = cn;
                    hloc[i] = O * tanhf(cn);
                }
                if (layer == 2) {
                    float4* hp = (float4*)&g_hist[t][mt * 32 + u][nb];
                    #pragma unroll
                    for (int i = 0; i < 4; i++)
                        hp[i] = make_float4(hloc[4 * i], hloc[4 * i + 1],
                                            hloc[4 * i + 2], hloc[4 * i + 3]);
                }
                #pragma unroll
                for (int i = 0; i < 16; i++)
                    sH[(n0 + i) * 33 + u] = hloc[i];
            }
            __syncthreads();

            // ---- transpose-write h as swizzled bf16 hi/lo images ----
            {
                const int n = tid >> 1, hf = tid & 1;
                const float* hr = &sH[n * 33 + hf * 16];
                uint32_t hw[8], lw[8];
                #pragma unroll
                for (int q = 0; q < 8; q++) {
                    float a = hr[2 * q], b = hr[2 * q + 1];
                    __nv_bfloat16 ah = __float2bfloat16(a), bh2 = __float2bfloat16(b);
                    __nv_bfloat16 al = __float2bfloat16(a - __bfloat162float(ah));
                    __nv_bfloat16 bl2 = __float2bfloat16(b - __bfloat162float(bh2));
                    hw[q] = (uint32_t)__bfloat16_as_ushort(ah)
                          | ((uint32_t)__bfloat16_as_ushort(bh2) << 16);
                    lw[q] = (uint32_t)__bfloat16_as_ushort(al)
                          | ((uint32_t)__bfloat16_as_ushort(bl2) << 16);
                }
                const int col = (mt & 1) * 64 + hf * 32;
                char* bh8 = (char*)&g_ab[layer][wp][0][nt][(mt >> 1) * 4096];
                char* bl8 = (char*)&g_ab[layer][wp][1][nt][(mt >> 1) * 4096];
                #pragma unroll
                for (int seg = 0; seg < 2; seg++) {
                    int off = n * 128 + col + seg * 16;
                    int sw  = swz(off);
                    *(uint4*)(bh8 + sw) = make_uint4(hw[4 * seg], hw[4 * seg + 1],
                                                     hw[4 * seg + 2], hw[4 * seg + 3]);
                    *(uint4*)(bl8 + sw) = make_uint4(lw[4 * seg], lw[4 * seg + 1],
                                                     lw[4 * seg + 2], lw[4 * seg + 3]);
                }
            }
        }
        grid_sync((unsigned)(s + 1));
    }
}

// ---------------------------------------------------------------------------
// Output head
// ---------------------------------------------------------------------------
__global__ void __launch_bounds__(256)
linear_head(const float* __restrict__ W_lin, const float* __restrict__ b_lin,
            float* __restrict__ out)
{
    __shared__ float sw[HD];
    const int t = blockIdx.x, b = threadIdx.x;
    sw[b] = W_lin[b];
    __syncthreads();
    const float* hp = &g_hist[t][0][0];
    float s = 0.f;
    #pragma unroll 8
    for (int k = 0; k < HD; k++)
        s += hp[(size_t)k * BB + b] * sw[k];
    out[(size_t)b * TT + t] = s + b_lin[0];
}

// ---------------------------------------------------------------------------
// 4 graph nodes: init -> prep -> persistent -> head
// ---------------------------------------------------------------------------
extern "C" void kernel_launch(void* const* d_in, const int* in_sizes, int n_in,
                              void* d_out, int out_size)
{
    const float* input = (const float*)d_in[0];
    const float* W_ih1 = (const float*)d_in[1];
    const float* W_hh1 = (const float*)d_in[2];
    const float* b_ih1 = (const float*)d_in[3];
    const float* b_hh1 = (const float*)d_in[4];
    const float* W_ih2 = (const float*)d_in[5];
    const float* W_hh2 = (const float*)d_in[6];
    const float* b_ih2 = (const float*)d_in[7];
    const float* b_hh2 = (const float*)d_in[8];
    const float* W_ih3 = (const float*)d_in[9];
    const float* W_hh3 = (const float*)d_in[10];
    const float* b_ih3 = (const float*)d_in[11];
    const float* b_hh3 = (const float*)d_in[12];
    const float* W_lin = (const float*)d_in[13];
    const float* b_lin = (const float*)d_in[14];
    float* out = (float*)d_out;

    cudaFuncSetAttribute(lstm_tc, cudaFuncAttributeMaxDynamicSharedMemorySize, SM_BYTES);

    init_state<<<256, 256>>>(input);
    prep_weights<<<512, 256>>>(W_hh1, W_ih2, W_hh2, W_ih3, W_hh3);
    lstm_tc<<<NB, NT, SM_BYTES>>>(W_ih1, b_ih1, b_hh1, b_ih2, b_hh2, b_ih3, b_hh3);
    linear_head<<<TT, 256>>>(W_lin, b_lin, out);
}

// round 15
// speedup vs baseline: 4.0138x; 1.4533x over previous
#include <cuda_runtime.h>
#include <cuda_bf16.h>
#include <cstdint>

#define HD 256
#define BB 256
#define TT 512
#define NB 96
#define NT 256

// ---- dynamic SMEM offsets (base manually 1024-aligned) ----
#define SM_BIAS  64           // 128 f32
#define SM_W1    640          // 128 f32
#define SM_STAGE 2048         // 2 bufs x 40KB
#define OFF_WHI  0
#define OFF_WLO  16384
#define OFF_ABF  32768
#define BUF_SZ   40960
#define SM_D     (SM_STAGE + 2 * BUF_SZ)       // 128 x 68 f32 = 34816
#define SM_H     (SM_D + 34816)                // 64 x 33 f32 = 8448
#define SM_BYTES (SM_H + 8448 + 1024)

// ---------------------------------------------------------------------------
// Global scratch (allocation-free)
// ---------------------------------------------------------------------------
__device__ __align__(16) __nv_bfloat16 g_wb[2][5][8][4 * 8192];  // swizzled W images (hi/lo)
__device__ __align__(16) __nv_bfloat16 g_ab[3][2][4][4 * 4096];  // swizzled act images (bf16)
__device__ float g_x[TT][BB];
__device__ float g_hist[TT][HD][BB];
__device__ int               g_bar_count;
__device__ volatile unsigned g_bar_gen;

// ---------------------------------------------------------------------------
// PTX helpers (sm_80+ base features — legal on compute_103)
// ---------------------------------------------------------------------------
__device__ __forceinline__ uint32_t s2u(const void* p) {
    uint32_t a;
    asm("{ .reg .u64 t; cvta.to.shared.u64 t, %1; cvt.u32.u64 %0, t; }" : "=r"(a) : "l"(p));
    return a;
}
#define CPA(dst, src) \
    asm volatile("cp.async.cg.shared.global [%0], [%1], 16;" \
        :: "r"(dst), "l"(__cvta_generic_to_global(src)))
#define CPC()  asm volatile("cp.async.commit_group;" ::: "memory")
#define CPW0() asm volatile("cp.async.wait_group 0;" ::: "memory")

#define LDSM4(r, a) \
    asm volatile("ldmatrix.sync.aligned.m8n8.x4.shared.b16 {%0,%1,%2,%3}, [%4];" \
        : "=r"((r)[0]), "=r"((r)[1]), "=r"((r)[2]), "=r"((r)[3]) : "r"(a))

__device__ __forceinline__ void mma16(float* d, const uint32_t* a, const uint32_t* b) {
    asm volatile("mma.sync.aligned.m16n8k16.row.col.f32.bf16.bf16.f32 "
        "{%0,%1,%2,%3}, {%4,%5,%6,%7}, {%8,%9}, {%0,%1,%2,%3};"
        : "+f"(d[0]), "+f"(d[1]), "+f"(d[2]), "+f"(d[3])
        : "r"(a[0]), "r"(a[1]), "r"(a[2]), "r"(a[3]), "r"(b[0]), "r"(b[1]));
}

__device__ __forceinline__ int swz(int o) { return o ^ ((o >> 3) & 0x70); }
__device__ __forceinline__ float sigf(float x) { return 1.f / (1.f + __expf(-x)); }

__device__ __forceinline__ void grid_sync(unsigned target) {
    __syncthreads();
    if (threadIdx.x == 0) {
        __threadfence();
        if (atomicAdd(&g_bar_count, 1) == NB - 1) {
            g_bar_count = 0;
            __threadfence();
            g_bar_gen = target;
        } else {
            while (g_bar_gen < target) { }
            __threadfence();
        }
    }
    __syncthreads();
}

// ---------------------------------------------------------------------------
// Prep: split fp32 weights to bf16 hi/lo, rows reordered (r = u*4+g), swizzled
// ---------------------------------------------------------------------------
__global__ void prep_weights(const float* __restrict__ A0, const float* __restrict__ A1,
                             const float* __restrict__ A2, const float* __restrict__ A3,
                             const float* __restrict__ A4)
{
    const float* mats[5] = { A0, A1, A2, A3, A4 };
    const int total = 5 * 8 * 128 * 256;
    for (int idx = blockIdx.x * blockDim.x + threadIdx.x; idx < total;
         idx += gridDim.x * blockDim.x) {
        int m  = idx / 262144, rem = idx % 262144;
        int mt = rem >> 15,    r2  = rem & 32767;
        int r  = r2 >> 8,      k   = r2 & 255;
        int orow = (r & 3) * 256 + mt * 32 + (r >> 2);
        float wv = mats[m][orow * HD + k];
        __nv_bfloat16 hi = __float2bfloat16(wv);
        __nv_bfloat16 lo = __float2bfloat16(wv - __bfloat162float(hi));
        int off = r * 128 + (k & 63) * 2;
        int di  = (k >> 6) * 8192 + (swz(off) >> 1);
        g_wb[0][m][mt][di] = hi;
        g_wb[1][m][mt][di] = lo;
    }
}

// ---------------------------------------------------------------------------
// Init: zero act images, reset barrier, transpose input
// ---------------------------------------------------------------------------
__global__ void init_state(const float* __restrict__ input)
{
    const int idx = blockIdx.x * blockDim.x + threadIdx.x;
    const int stride = gridDim.x * blockDim.x;
    if (idx == 0) { g_bar_count = 0; g_bar_gen = 0; }
    uint4* az = (uint4*)&g_ab[0][0][0][0];
    const int nz = (int)(sizeof(g_ab) / 16);
    for (int i = idx; i < nz; i += stride) az[i] = make_uint4(0, 0, 0, 0);
    for (int i = idx; i < TT * BB; i += stride) {
        int t = i >> 8, b = i & 255;
        g_x[t][b] = input[(size_t)b * TT + t];
    }
}

// ---------------------------------------------------------------------------
// Stage one K-chunk: Whi 16KB + Wlo 16KB + abf 8KB (10 cp.async / thread)
// ---------------------------------------------------------------------------
__device__ __forceinline__ void stage_chunk(uint32_t bd,
    const __nv_bfloat16* whi, const __nv_bfloat16* wlo,
    const __nv_bfloat16* abf, int tid)
{
    #pragma unroll
    for (int q = 0; q < 4; q++) {
        uint32_t o = (uint32_t)(q * 256 + tid) * 16;
        CPA(bd + OFF_WHI + o, (const char*)whi + o);
        CPA(bd + OFF_WLO + o, (const char*)wlo + o);
    }
    #pragma unroll
    for (int q = 0; q < 2; q++) {
        uint32_t o = (uint32_t)(q * 256 + tid) * 16;
        CPA(bd + OFF_ABF + o, (const char*)abf + o);
    }
}

// ---------------------------------------------------------------------------
// Compute one chunk (K=64): 2 split terms, 1 m-tile x 8 n-tiles per warp
// ---------------------------------------------------------------------------
__device__ __forceinline__ void compute_chunk(uint32_t bd, float acc[8][4],
                                              int a_off0, int b_off0)
{
    const uint32_t whi_b = bd + OFF_WHI, wlo_b = bd + OFF_WLO;
    const uint32_t ab_b  = bd + OFF_ABF;
    #pragma unroll
    for (int ks = 0; ks < 4; ks++) {
        uint32_t ah[4], al[4];
        const int oa = a_off0 + ks * 32;
        LDSM4(ah, whi_b + swz(oa));
        LDSM4(al, wlo_b + swz(oa));
        uint32_t bb[4][4];
        #pragma unroll
        for (int np = 0; np < 4; np++) {
            const int ob = b_off0 + np * 2048 + ks * 32;
            LDSM4(bb[np], ab_b + swz(ob));
        }
        #pragma unroll
        for (int ni = 0; ni < 8; ni++) {
            const uint32_t* bp = &bb[ni >> 1][(ni & 1) * 2];
            mma16(acc[ni], ah, bp);   // Whi * abf
            mma16(acc[ni], al, bp);   // Wlo * abf
        }
    }
}

// ---------------------------------------------------------------------------
// Persistent HMMA LSTM: 96 CTAs = 3 layers x 8 mtiles x 4 ntiles, 8 warps
// ---------------------------------------------------------------------------
__global__ void __launch_bounds__(NT, 1)
lstm_tc(const float* __restrict__ W_ih1,
        const float* __restrict__ b_ih1, const float* __restrict__ b_hh1,
        const float* __restrict__ b_ih2, const float* __restrict__ b_hh2,
        const float* __restrict__ b_ih3, const float* __restrict__ b_hh3)
{
    extern __shared__ __align__(16) unsigned char smraw[];
    char* smp = (char*)(((uintptr_t)smraw + 1023) & ~(uintptr_t)1023);
    const uint32_t sb = s2u(smp);

    const int tid = threadIdx.x;
    const int w   = tid >> 5, l = tid & 31;
    const int layer = blockIdx.x >> 5;
    const int mt = (blockIdx.x & 31) >> 2;
    const int nt = blockIdx.x & 3;

    // fused bias + layer-1 input column (reordered rows)
    if (tid < 128) {
        const float* bi = (layer == 0) ? b_ih1 : (layer == 1) ? b_ih2 : b_ih3;
        const float* bh = (layer == 0) ? b_hh1 : (layer == 1) ? b_hh2 : b_hh3;
        int orow = (tid & 3) * 256 + mt * 32 + (tid >> 2);
        ((float*)(smp + SM_BIAS))[tid] = bi[orow] + bh[orow];
        ((float*)(smp + SM_W1))[tid]   = (layer == 0) ? W_ih1[orow] : 0.f;
    }
    __syncthreads();

    // ldmatrix lane base offsets: warp w owns A rows w*16..w*16+15
    const int a_off0 = (w * 16 + (l & 15)) * 128 + (l >> 4) * 16;
    const int b_off0 = ((l & 7) + ((l >> 4) & 1) * 8) * 128 + ((l >> 3) & 1) * 16;

    float cst[8];
    #pragma unroll
    for (int i = 0; i < 8; i++) cst[i] = 0.f;

    const int u = tid >> 3, n0 = (tid & 7) * 8;   // pointwise: unit u, 8 batches
    float* sD = (float*)(smp + SM_D);
    float* sH = (float*)(smp + SM_H);

    #pragma unroll 1
    for (int s = 0; s < TT + 2; s++) {
        const int rp = (s + 1) & 1, wp = s & 1;
        const int t = s - layer;
        if (t >= 0 && t < TT) {
            const int NQ = (layer == 0) ? 4 : 8;
            float acc[8][4];
            #pragma unroll
            for (int ni = 0; ni < 8; ni++)
                #pragma unroll
                for (int e = 0; e < 4; e++) acc[ni][e] = 0.f;

            // chunk q -> (matrix m = q>>2, kchunk kc = q&3)
            auto chunk_ptrs = [&](int q, const __nv_bfloat16*& whi,
                                  const __nv_bfloat16*& wlo, const __nv_bfloat16*& abf) {
                int m = q >> 2, kc = q & 3;
                int mi_, srcL;
                if (layer == 0)      { mi_ = 0;          srcL = 0; }
                else if (layer == 1) { mi_ = m ? 2 : 1;  srcL = m ? 1 : 0; }
                else                 { mi_ = m ? 4 : 3;  srcL = m ? 2 : 1; }
                whi = &g_wb[0][mi_][mt][kc * 8192];
                wlo = &g_wb[1][mi_][mt][kc * 8192];
                abf = &g_ab[srcL][rp][nt][kc * 4096];
            };

            {   // prologue: stage chunk 0
                const __nv_bfloat16 *whi, *wlo, *abf;
                chunk_ptrs(0, whi, wlo, abf);
                stage_chunk(sb + SM_STAGE, whi, wlo, abf, tid);
                CPC();
            }
            #pragma unroll 1
            for (int q = 0; q < NQ; q++) {
                CPW0();
                __syncthreads();
                if (q + 1 < NQ) {
                    const __nv_bfloat16 *whi, *wlo, *abf;
                    chunk_ptrs(q + 1, whi, wlo, abf);
                    stage_chunk(sb + SM_STAGE + ((q + 1) & 1) * BUF_SZ, whi, wlo, abf, tid);
                    CPC();
                }
                compute_chunk(sb + SM_STAGE + (q & 1) * BUF_SZ, acc, a_off0, b_off0);
            }

            // ---- store D frags to SMEM [128][68] ----
            {
                const int row0 = w * 16 + (l >> 2);
                const int colb = (l & 3) * 2;
                #pragma unroll
                for (int ni = 0; ni < 8; ni++) {
                    float2* p0 = (float2*)&sD[row0 * 68 + ni * 8 + colb];
                    float2* p1 = (float2*)&sD[(row0 + 8) * 68 + ni * 8 + colb];
                    *p0 = make_float2(acc[ni][0], acc[ni][1]);
                    *p1 = make_float2(acc[ni][2], acc[ni][3]);
                }
            }
            __syncthreads();

            // ---- pointwise LSTM cell: thread = (unit u, batch octet n0) ----
            {
                const float* q0 = &sD[(4 * u + 0) * 68 + n0];
                const float* q1 = &sD[(4 * u + 1) * 68 + n0];
                const float* q2 = &sD[(4 * u + 2) * 68 + n0];
                const float* q3 = &sD[(4 * u + 3) * 68 + n0];
                const float b0 = ((float*)(smp + SM_BIAS))[4 * u + 0];
                const float b1 = ((float*)(smp + SM_BIAS))[4 * u + 1];
                const float b2 = ((float*)(smp + SM_BIAS))[4 * u + 2];
                const float b3 = ((float*)(smp + SM_BIAS))[4 * u + 3];
                float w0 = 0.f, w1 = 0.f, w2 = 0.f, w3 = 0.f;
                if (layer == 0) {
                    w0 = ((float*)(smp + SM_W1))[4 * u + 0];
                    w1 = ((float*)(smp + SM_W1))[4 * u + 1];
                    w2 = ((float*)(smp + SM_W1))[4 * u + 2];
                    w3 = ((float*)(smp + SM_W1))[4 * u + 3];
                }
                const int nb = nt * 64 + n0;
                float hloc[8];
                #pragma unroll
                for (int i = 0; i < 8; i++) {
                    float gi = q0[i] + b0, gf = q1[i] + b1;
                    float gg = q2[i] + b2, go = q3[i] + b3;
                    if (layer == 0) {
                        float xv = g_x[t][nb + i];
                        gi += w0 * xv; gf += w1 * xv; gg += w2 * xv; go += w3 * xv;
                    }
                    float I = sigf(gi), F = sigf(gf), G = tanhf(gg), O = sigf(go);
                    float cn = F * cst[i] + I * G;
                    cst[i] = cn;
                    hloc[i] = O * tanhf(cn);
                }
                if (layer == 2) {
                    float4* hp = (float4*)&g_hist[t][mt * 32 + u][nb];
                    hp[0] = make_float4(hloc[0], hloc[1], hloc[2], hloc[3]);
                    hp[1] = make_float4(hloc[4], hloc[5], hloc[6], hloc[7]);
                }
                #pragma unroll
                for (int i = 0; i < 8; i++)
                    sH[(n0 + i) * 33 + u] = hloc[i];
            }
            __syncthreads();

            // ---- transpose-write h as swizzled bf16 image (round-to-nearest) ----
            {
                const int n = tid >> 2, q = tid & 3;   // n-row, unit-octet
                const float* hr = &sH[n * 33 + q * 8];
                uint32_t hw[4];
                #pragma unroll
                for (int e = 0; e < 4; e++) {
                    __nv_bfloat16 ah = __float2bfloat16(hr[2 * e]);
                    __nv_bfloat16 bh2 = __float2bfloat16(hr[2 * e + 1]);
                    hw[e] = (uint32_t)__bfloat16_as_ushort(ah)
                          | ((uint32_t)__bfloat16_as_ushort(bh2) << 16);
                }
                char* img = (char*)&g_ab[layer][wp][nt][(mt >> 1) * 4096];
                int off = n * 128 + (mt & 1) * 64 + q * 16;
                *(uint4*)(img + swz(off)) = make_uint4(hw[0], hw[1], hw[2], hw[3]);
            }
        }
        grid_sync((unsigned)(s + 1));
    }
}

// ---------------------------------------------------------------------------
// Output head
// ---------------------------------------------------------------------------
__global__ void __launch_bounds__(256)
linear_head(const float* __restrict__ W_lin, const float* __restrict__ b_lin,
            float* __restrict__ out)
{
    __shared__ float sw[HD];
    const int t = blockIdx.x, b = threadIdx.x;
    sw[b] = W_lin[b];
    __syncthreads();
    const float* hp = &g_hist[t][0][0];
    float s = 0.f;
    #pragma unroll 8
    for (int k = 0; k < HD; k++)
        s += hp[(size_t)k * BB + b] * sw[k];
    out[(size_t)b * TT + t] = s + b_lin[0];
}

// ---------------------------------------------------------------------------
// 4 graph nodes: init -> prep -> persistent -> head
// ---------------------------------------------------------------------------
extern "C" void kernel_launch(void* const* d_in, const int* in_sizes, int n_in,
                              void* d_out, int out_size)
{
    const float* input = (const float*)d_in[0];
    const float* W_ih1 = (const float*)d_in[1];
    const float* W_hh1 = (const float*)d_in[2];
    const float* b_ih1 = (const float*)d_in[3];
    const float* b_hh1 = (const float*)d_in[4];
    const float* W_ih2 = (const float*)d_in[5];
    const float* W_hh2 = (const float*)d_in[6];
    const float* b_ih2 = (const float*)d_in[7];
    const float* b_hh2 = (const float*)d_in[8];
    const float* W_ih3 = (const float*)d_in[9];
    const float* W_hh3 = (const float*)d_in[10];
    const float* b_ih3 = (const float*)d_in[11];
    const float* b_hh3 = (const float*)d_in[12];
    const float* W_lin = (const float*)d_in[13];
    const float* b_lin = (const float*)d_in[14];
    float* out = (float*)d_out;

    cudaFuncSetAttribute(lstm_tc, cudaFuncAttributeMaxDynamicSharedMemorySize, SM_BYTES);

    init_state<<<256, 256>>>(input);
    prep_weights<<<512, 256>>>(W_hh1, W_ih2, W_hh2, W_ih3, W_hh3);
    lstm_tc<<<NB, NT, SM_BYTES>>>(W_ih1, b_ih1, b_hh1, b_ih2, b_hh2, b_ih3, b_hh3);
    linear_head<<<TT, 256>>>(W_lin, b_lin, out);
}

// round 16
// speedup vs baseline: 4.7335x; 1.1793x over previous
#include <cuda_runtime.h>
#include <cuda_fp16.h>
#include <cstdint>

#define HD 256
#define BB 256
#define TT 512
#define NB 96
#define NT 256

// ---- dynamic SMEM offsets (base manually 1024-aligned) ----
#define SM_BIAS  64           // 128 f32
#define SM_W1    640          // 128 f32
#define SM_STAGE 2048         // 2 bufs x 24KB
#define OFF_W    0
#define OFF_ABF  16384
#define BUF_SZ   24576
#define SM_D     (SM_STAGE + 2 * BUF_SZ)       // 128 x 68 f32 = 34816
#define SM_H     (SM_D + 34816)                // 64 x 33 f32 = 8448
#define SM_BYTES (SM_H + 8448 + 1024)

// ---------------------------------------------------------------------------
// Global scratch (allocation-free)
// ---------------------------------------------------------------------------
__device__ __align__(16) __half g_wb[5][8][4 * 8192];   // swizzled fp16 W images
__device__ __align__(16) __half g_ab[3][2][4][4 * 4096]; // swizzled fp16 act images
__device__ float g_x[TT][BB];
__device__ float g_hist[TT][HD][BB];
__device__ int               g_bar_count;
__device__ volatile unsigned g_bar_gen;

// ---------------------------------------------------------------------------
// PTX helpers (sm_80+ base features — legal on compute_103)
// ---------------------------------------------------------------------------
__device__ __forceinline__ uint32_t s2u(const void* p) {
    uint32_t a;
    asm("{ .reg .u64 t; cvta.to.shared.u64 t, %1; cvt.u32.u64 %0, t; }" : "=r"(a) : "l"(p));
    return a;
}
#define CPA(dst, src) \
    asm volatile("cp.async.cg.shared.global [%0], [%1], 16;" \
        :: "r"(dst), "l"(__cvta_generic_to_global(src)))
#define CPC()  asm volatile("cp.async.commit_group;" ::: "memory")
#define CPW0() asm volatile("cp.async.wait_group 0;" ::: "memory")

#define LDSM4(r, a) \
    asm volatile("ldmatrix.sync.aligned.m8n8.x4.shared.b16 {%0,%1,%2,%3}, [%4];" \
        : "=r"((r)[0]), "=r"((r)[1]), "=r"((r)[2]), "=r"((r)[3]) : "r"(a))

__device__ __forceinline__ void mma16(float* d, const uint32_t* a, const uint32_t* b) {
    asm volatile("mma.sync.aligned.m16n8k16.row.col.f32.f16.f16.f32 "
        "{%0,%1,%2,%3}, {%4,%5,%6,%7}, {%8,%9}, {%0,%1,%2,%3};"
        : "+f"(d[0]), "+f"(d[1]), "+f"(d[2]), "+f"(d[3])
        : "r"(a[0]), "r"(a[1]), "r"(a[2]), "r"(a[3]), "r"(b[0]), "r"(b[1]));
}

__device__ __forceinline__ int swz(int o) { return o ^ ((o >> 3) & 0x70); }
__device__ __forceinline__ float sigf(float x) { return 1.f / (1.f + __expf(-x)); }

__device__ __forceinline__ void grid_sync(unsigned target) {
    __syncthreads();
    if (threadIdx.x == 0) {
        __threadfence();
        if (atomicAdd(&g_bar_count, 1) == NB - 1) {
            g_bar_count = 0;
            __threadfence();
            g_bar_gen = target;
        } else {
            while (g_bar_gen < target) { }
            __threadfence();
        }
    }
    __syncthreads();
}

// ---------------------------------------------------------------------------
// Prep: fp32 weights -> fp16, rows reordered (r = u*4+g), swizzled image
// ---------------------------------------------------------------------------
__global__ void prep_weights(const float* __restrict__ A0, const float* __restrict__ A1,
                             const float* __restrict__ A2, const float* __restrict__ A3,
                             const float* __restrict__ A4)
{
    const float* mats[5] = { A0, A1, A2, A3, A4 };
    const int total = 5 * 8 * 128 * 256;
    for (int idx = blockIdx.x * blockDim.x + threadIdx.x; idx < total;
         idx += gridDim.x * blockDim.x) {
        int m  = idx / 262144, rem = idx % 262144;
        int mt = rem >> 15,    r2  = rem & 32767;
        int r  = r2 >> 8,      k   = r2 & 255;
        int orow = (r & 3) * 256 + mt * 32 + (r >> 2);
        float wv = mats[m][orow * HD + k];
        int off = r * 128 + (k & 63) * 2;
        int di  = (k >> 6) * 8192 + (swz(off) >> 1);
        g_wb[m][mt][di] = __float2half_rn(wv);
    }
}

// ---------------------------------------------------------------------------
// Init: zero act images, reset barrier, transpose input
// ---------------------------------------------------------------------------
__global__ void init_state(const float* __restrict__ input)
{
    const int idx = blockIdx.x * blockDim.x + threadIdx.x;
    const int stride = gridDim.x * blockDim.x;
    if (idx == 0) { g_bar_count = 0; g_bar_gen = 0; }
    uint4* az = (uint4*)&g_ab[0][0][0][0];
    const int nz = (int)(sizeof(g_ab) / 16);
    for (int i = idx; i < nz; i += stride) az[i] = make_uint4(0, 0, 0, 0);
    for (int i = idx; i < TT * BB; i += stride) {
        int t = i >> 8, b = i & 255;
        g_x[t][b] = input[(size_t)b * TT + t];
    }
}

// ---------------------------------------------------------------------------
// Stage one K-chunk: W 16KB + act 8KB (6 cp.async / thread, 256 threads)
// ---------------------------------------------------------------------------
__device__ __forceinline__ void stage_chunk(uint32_t bd,
    const __half* wsl, const __half* abf, int tid)
{
    #pragma unroll
    for (int q = 0; q < 4; q++) {
        uint32_t o = (uint32_t)(q * 256 + tid) * 16;
        CPA(bd + OFF_W + o, (const char*)wsl + o);
    }
    #pragma unroll
    for (int q = 0; q < 2; q++) {
        uint32_t o = (uint32_t)(q * 256 + tid) * 16;
        CPA(bd + OFF_ABF + o, (const char*)abf + o);
    }
}

// ---------------------------------------------------------------------------
// Compute one chunk (K=64): single fp16 term, 1 m-tile x 8 n-tiles per warp
// ---------------------------------------------------------------------------
__device__ __forceinline__ void compute_chunk(uint32_t bd, float acc[8][4],
                                              int a_off0, int b_off0)
{
    const uint32_t w_b = bd + OFF_W, ab_b = bd + OFF_ABF;
    #pragma unroll
    for (int ks = 0; ks < 4; ks++) {
        uint32_t ah[4];
        LDSM4(ah, w_b + swz(a_off0 + ks * 32));
        uint32_t bb[4][4];
        #pragma unroll
        for (int np = 0; np < 4; np++)
            LDSM4(bb[np], ab_b + swz(b_off0 + np * 2048 + ks * 32));
        #pragma unroll
        for (int ni = 0; ni < 8; ni++)
            mma16(acc[ni], ah, &bb[ni >> 1][(ni & 1) * 2]);
    }
}

// ---------------------------------------------------------------------------
// Persistent HMMA LSTM: 96 CTAs = 3 layers x 8 mtiles x 4 ntiles, 8 warps
// ---------------------------------------------------------------------------
__global__ void __launch_bounds__(NT, 1)
lstm_tc(const float* __restrict__ W_ih1,
        const float* __restrict__ b_ih1, const float* __restrict__ b_hh1,
        const float* __restrict__ b_ih2, const float* __restrict__ b_hh2,
        const float* __restrict__ b_ih3, const float* __restrict__ b_hh3)
{
    extern __shared__ __align__(16) unsigned char smraw[];
    char* smp = (char*)(((uintptr_t)smraw + 1023) & ~(uintptr_t)1023);
    const uint32_t sb = s2u(smp);

    const int tid = threadIdx.x;
    const int w   = tid >> 5, l = tid & 31;
    const int layer = blockIdx.x >> 5;
    const int mt = (blockIdx.x & 31) >> 2;
    const int nt = blockIdx.x & 3;

    // fused bias + layer-1 input column (reordered rows)
    if (tid < 128) {
        const float* bi = (layer == 0) ? b_ih1 : (layer == 1) ? b_ih2 : b_ih3;
        const float* bh = (layer == 0) ? b_hh1 : (layer == 1) ? b_hh2 : b_hh3;
        int orow = (tid & 3) * 256 + mt * 32 + (tid >> 2);
        ((float*)(smp + SM_BIAS))[tid] = bi[orow] + bh[orow];
        ((float*)(smp + SM_W1))[tid]   = (layer == 0) ? W_ih1[orow] : 0.f;
    }
    __syncthreads();

    // ldmatrix lane base offsets: warp w owns A rows w*16..w*16+15
    const int a_off0 = (w * 16 + (l & 15)) * 128 + (l >> 4) * 16;
    const int b_off0 = ((l & 7) + ((l >> 4) & 1) * 8) * 128 + ((l >> 3) & 1) * 16;

    float cst[8];
    #pragma unroll
    for (int i = 0; i < 8; i++) cst[i] = 0.f;

    const int u = tid >> 3, n0 = (tid & 7) * 8;   // pointwise: unit u, 8 batches
    float* sD = (float*)(smp + SM_D);
    float* sH = (float*)(smp + SM_H);

    #pragma unroll 1
    for (int s = 0; s < TT + 2; s++) {
        const int rp = (s + 1) & 1, wp = s & 1;
        const int t = s - layer;
        if (t >= 0 && t < TT) {
            const int NQ = (layer == 0) ? 4 : 8;
            float acc[8][4];
            #pragma unroll
            for (int ni = 0; ni < 8; ni++)
                #pragma unroll
                for (int e = 0; e < 4; e++) acc[ni][e] = 0.f;

            // chunk q -> (matrix m = q>>2, kchunk kc = q&3)
            auto chunk_ptrs = [&](int q, const __half*& wsl, const __half*& abf) {
                int m = q >> 2, kc = q & 3;
                int mi_, srcL;
                if (layer == 0)      { mi_ = 0;          srcL = 0; }
                else if (layer == 1) { mi_ = m ? 2 : 1;  srcL = m ? 1 : 0; }
                else                 { mi_ = m ? 4 : 3;  srcL = m ? 2 : 1; }
                wsl = &g_wb[mi_][mt][kc * 8192];
                abf = &g_ab[srcL][rp][nt][kc * 4096];
            };

            {   // prologue: stage chunk 0
                const __half *wsl, *abf;
                chunk_ptrs(0, wsl, abf);
                stage_chunk(sb + SM_STAGE, wsl, abf, tid);
                CPC();
            }
            #pragma unroll 1
            for (int q = 0; q < NQ; q++) {
                CPW0();
                __syncthreads();
                if (q + 1 < NQ) {
                    const __half *wsl, *abf;
                    chunk_ptrs(q + 1, wsl, abf);
                    stage_chunk(sb + SM_STAGE + ((q + 1) & 1) * BUF_SZ, wsl, abf, tid);
                    CPC();
                }
                compute_chunk(sb + SM_STAGE + (q & 1) * BUF_SZ, acc, a_off0, b_off0);
            }

            // ---- store D frags to SMEM [128][68] ----
            {
                const int row0 = w * 16 + (l >> 2);
                const int colb = (l & 3) * 2;
                #pragma unroll
                for (int ni = 0; ni < 8; ni++) {
                    float2* p0 = (float2*)&sD[row0 * 68 + ni * 8 + colb];
                    float2* p1 = (float2*)&sD[(row0 + 8) * 68 + ni * 8 + colb];
                    *p0 = make_float2(acc[ni][0], acc[ni][1]);
                    *p1 = make_float2(acc[ni][2], acc[ni][3]);
                }
            }
            __syncthreads();

            // ---- pointwise LSTM cell: thread = (unit u, batch octet n0) ----
            {
                const float* q0 = &sD[(4 * u + 0) * 68 + n0];
                const float* q1 = &sD[(4 * u + 1) * 68 + n0];
                const float* q2 = &sD[(4 * u + 2) * 68 + n0];
                const float* q3 = &sD[(4 * u + 3) * 68 + n0];
                const float b0 = ((float*)(smp + SM_BIAS))[4 * u + 0];
                const float b1 = ((float*)(smp + SM_BIAS))[4 * u + 1];
                const float b2 = ((float*)(smp + SM_BIAS))[4 * u + 2];
                const float b3 = ((float*)(smp + SM_BIAS))[4 * u + 3];
                float w0 = 0.f, w1 = 0.f, w2 = 0.f, w3 = 0.f;
                if (layer == 0) {
                    w0 = ((float*)(smp + SM_W1))[4 * u + 0];
                    w1 = ((float*)(smp + SM_W1))[4 * u + 1];
                    w2 = ((float*)(smp + SM_W1))[4 * u + 2];
                    w3 = ((float*)(smp + SM_W1))[4 * u + 3];
                }
                const int nb = nt * 64 + n0;
                float hloc[8];
                #pragma unroll
                for (int i = 0; i < 8; i++) {
                    float gi = q0[i] + b0, gf = q1[i] + b1;
                    float gg = q2[i] + b2, go = q3[i] + b3;
                    if (layer == 0) {
                        float xv = g_x[t][nb + i];
                        gi += w0 * xv; gf += w1 * xv; gg += w2 * xv; go += w3 * xv;
                    }
                    float I = sigf(gi), F = sigf(gf), G = tanhf(gg), O = sigf(go);
                    float cn = F * cst[i] + I * G;
                    cst[i] = cn;
                    hloc[i] = O * tanhf(cn);
                }
                if (layer == 2) {
                    float4* hp = (float4*)&g_hist[t][mt * 32 + u][nb];
                    hp[0] = make_float4(hloc[0], hloc[1], hloc[2], hloc[3]);
                    hp[1] = make_float4(hloc[4], hloc[5], hloc[6], hloc[7]);
                }
                #pragma unroll
                for (int i = 0; i < 8; i++)
                    sH[(n0 + i) * 33 + u] = hloc[i];
            }
            __syncthreads();

            // ---- transpose-write h as swizzled fp16 image ----
            {
                const int n = tid >> 2, q = tid & 3;   // n-row, unit-octet
                const float* hr = &sH[n * 33 + q * 8];
                uint32_t hw[4];
                #pragma unroll
                for (int e = 0; e < 4; e++) {
                    __half ah = __float2half_rn(hr[2 * e]);
                    __half bh2 = __float2half_rn(hr[2 * e + 1]);
                    hw[e] = (uint32_t)__half_as_ushort(ah)
                          | ((uint32_t)__half_as_ushort(bh2) << 16);
                }
                char* img = (char*)&g_ab[layer][wp][nt][(mt >> 1) * 4096];
                int off = n * 128 + (mt & 1) * 64 + q * 16;
                *(uint4*)(img + swz(off)) = make_uint4(hw[0], hw[1], hw[2], hw[3]);
            }
        }
        grid_sync((unsigned)(s + 1));
    }
}

// ---------------------------------------------------------------------------
// Output head
// ---------------------------------------------------------------------------
__global__ void __launch_bounds__(256)
linear_head(const float* __restrict__ W_lin, const float* __restrict__ b_lin,
            float* __restrict__ out)
{
    __shared__ float sw[HD];
    const int t = blockIdx.x, b = threadIdx.x;
    sw[b] = W_lin[b];
    __syncthreads();
    const float* hp = &g_hist[t][0][0];
    float s = 0.f;
    #pragma unroll 8
    for (int k = 0; k < HD; k++)
        s += hp[(size_t)k * BB + b] * sw[k];
    out[(size_t)b * TT + t] = s + b_lin[0];
}

// ---------------------------------------------------------------------------
// 4 graph nodes: init -> prep -> persistent -> head
// ---------------------------------------------------------------------------
extern "C" void kernel_launch(void* const* d_in, const int* in_sizes, int n_in,
                              void* d_out, int out_size)
{
    const float* input = (const float*)d_in[0];
    const float* W_ih1 = (const float*)d_in[1];
    const float* W_hh1 = (const float*)d_in[2];
    const float* b_ih1 = (const float*)d_in[3];
    const float* b_hh1 = (const float*)d_in[4];
    const float* W_ih2 = (const float*)d_in[5];
    const float* W_hh2 = (const float*)d_in[6];
    const float* b_ih2 = (const float*)d_in[7];
    const float* b_hh2 = (const float*)d_in[8];
    const float* W_ih3 = (const float*)d_in[9];
    const float* W_hh3 = (const float*)d_in[10];
    const float* b_ih3 = (const float*)d_in[11];
    const float* b_hh3 = (const float*)d_in[12];
    const float* W_lin = (const float*)d_in[13];
    const float* b_lin = (const float*)d_in[14];
    float* out = (float*)d_out;

    cudaFuncSetAttribute(lstm_tc, cudaFuncAttributeMaxDynamicSharedMemorySize, SM_BYTES);

    init_state<<<256, 256>>>(input);
    prep_weights<<<512, 256>>>(W_hh1, W_ih2, W_hh2, W_ih3, W_hh3);
    lstm_tc<<<NB, NT, SM_BYTES>>>(W_ih1, b_ih1, b_hh1, b_ih2, b_hh2, b_ih3, b_hh3);
    linear_head<<<TT, 256>>>(W_lin, b_lin, out);
}

// round 17
// speedup vs baseline: 5.5444x; 1.1713x over previous
#include <cuda_runtime.h>
#include <cuda_fp16.h>
#include <cstdint>

#define HD 256
#define BB 256
#define TT 512
#define NB 96
#define NT 256

// ---- dynamic SMEM offsets (base manually 1024-aligned) ----
#define SM_BIAS  64            // 128 f32
#define SM_W1    640           // 128 f32
#define SM_WRES  2048          // resident W: up to 2 matrices x 64KB
#define SM_ACT   133120        // act double buffer: 2 x 32KB
#define ABUF_SZ  32768
#define SM_D     SM_ACT        // epilogue overlay onto act region (34816 <= 65536)
#define SM_H     198656        // 64 x 33 f32 = 8448
#define SM_BYTES (SM_H + 8448 + 1024)

// ---------------------------------------------------------------------------
// Global scratch (allocation-free)
// ---------------------------------------------------------------------------
__device__ __align__(16) __half g_wb[5][8][4 * 8192];    // swizzled fp16 W images
__device__ __align__(16) __half g_ab[3][2][4][4 * 4096]; // swizzled fp16 act images
__device__ float g_x[TT][BB];
__device__ float g_hist[TT][HD][BB];
__device__ int               g_bar_count;
__device__ volatile unsigned g_bar_gen;

// ---------------------------------------------------------------------------
// PTX helpers (sm_80+ base features — legal on compute_103)
// ---------------------------------------------------------------------------
__device__ __forceinline__ uint32_t s2u(const void* p) {
    uint32_t a;
    asm("{ .reg .u64 t; cvta.to.shared.u64 t, %1; cvt.u32.u64 %0, t; }" : "=r"(a) : "l"(p));
    return a;
}
#define CPA(dst, src) \
    asm volatile("cp.async.cg.shared.global [%0], [%1], 16;" \
        :: "r"(dst), "l"(__cvta_generic_to_global(src)))
#define CPC()   asm volatile("cp.async.commit_group;" ::: "memory")
#define CPW(n)  asm volatile("cp.async.wait_group %0;" :: "n"(n) : "memory")

#define LDSM4(r, a) \
    asm volatile("ldmatrix.sync.aligned.m8n8.x4.shared.b16 {%0,%1,%2,%3}, [%4];" \
        : "=r"((r)[0]), "=r"((r)[1]), "=r"((r)[2]), "=r"((r)[3]) : "r"(a))

__device__ __forceinline__ void mma16(float* d, const uint32_t* a, const uint32_t* b) {
    asm volatile("mma.sync.aligned.m16n8k16.row.col.f32.f16.f16.f32 "
        "{%0,%1,%2,%3}, {%4,%5,%6,%7}, {%8,%9}, {%0,%1,%2,%3};"
        : "+f"(d[0]), "+f"(d[1]), "+f"(d[2]), "+f"(d[3])
        : "r"(a[0]), "r"(a[1]), "r"(a[2]), "r"(a[3]), "r"(b[0]), "r"(b[1]));
}

__device__ __forceinline__ int swz(int o) { return o ^ ((o >> 3) & 0x70); }
__device__ __forceinline__ float sigf(float x) { return 1.f / (1.f + __expf(-x)); }

__device__ __forceinline__ void grid_sync(unsigned target) {
    __syncthreads();
    if (threadIdx.x == 0) {
        __threadfence();
        if (atomicAdd(&g_bar_count, 1) == NB - 1) {
            g_bar_count = 0;
            __threadfence();
            g_bar_gen = target;
        } else {
            while (g_bar_gen < target) { }
            __threadfence();
        }
    }
    __syncthreads();
}

// ---------------------------------------------------------------------------
// Prep: fp32 weights -> fp16, rows reordered (r = u*4+g), swizzled image
// ---------------------------------------------------------------------------
__global__ void prep_weights(const float* __restrict__ A0, const float* __restrict__ A1,
                             const float* __restrict__ A2, const float* __restrict__ A3,
                             const float* __restrict__ A4)
{
    const float* mats[5] = { A0, A1, A2, A3, A4 };
    const int total = 5 * 8 * 128 * 256;
    for (int idx = blockIdx.x * blockDim.x + threadIdx.x; idx < total;
         idx += gridDim.x * blockDim.x) {
        int m  = idx / 262144, rem = idx % 262144;
        int mt = rem >> 15,    r2  = rem & 32767;
        int r  = r2 >> 8,      k   = r2 & 255;
        int orow = (r & 3) * 256 + mt * 32 + (r >> 2);
        float wv = mats[m][orow * HD + k];
        int off = r * 128 + (k & 63) * 2;
        int di  = (k >> 6) * 8192 + (swz(off) >> 1);
        g_wb[m][mt][di] = __float2half_rn(wv);
    }
}

// ---------------------------------------------------------------------------
// Init: zero act images, reset barrier, transpose input
// ---------------------------------------------------------------------------
__global__ void init_state(const float* __restrict__ input)
{
    const int idx = blockIdx.x * blockDim.x + threadIdx.x;
    const int stride = gridDim.x * blockDim.x;
    if (idx == 0) { g_bar_count = 0; g_bar_gen = 0; }
    uint4* az = (uint4*)&g_ab[0][0][0][0];
    const int nz = (int)(sizeof(g_ab) / 16);
    for (int i = idx; i < nz; i += stride) az[i] = make_uint4(0, 0, 0, 0);
    for (int i = idx; i < TT * BB; i += stride) {
        int t = i >> 8, b = i & 255;
        g_x[t][b] = input[(size_t)b * TT + t];
    }
}

// ---------------------------------------------------------------------------
// Stage one full act image (32KB = K256 x N64) into buffer (8 cp.async/thr)
// ---------------------------------------------------------------------------
__device__ __forceinline__ void stage_act(uint32_t dst, const __half* abf, int tid)
{
    const char* a8 = (const char*)abf;
    #pragma unroll
    for (int q = 0; q < 8; q++) {
        uint32_t o = (uint32_t)(q * 256 + tid) * 16;
        CPA(dst + o, a8 + o);
    }
}

// ---------------------------------------------------------------------------
// Full K=256 MMA pass: W resident in SMEM, act in staged buffer
// ---------------------------------------------------------------------------
__device__ __forceinline__ void compute_mat(uint32_t wbase, uint32_t abase,
                                            float acc[8][4], int a_off0, int b_off0)
{
    #pragma unroll
    for (int kc = 0; kc < 4; kc++) {
        const uint32_t wb = wbase + kc * 16384;
        const uint32_t ab = abase + kc * 8192;
        #pragma unroll
        for (int ks = 0; ks < 4; ks++) {
            uint32_t ah[4];
            LDSM4(ah, wb + swz(a_off0 + ks * 32));
            uint32_t bb[4][4];
            #pragma unroll
            for (int np = 0; np < 4; np++)
                LDSM4(bb[np], ab + swz(b_off0 + np * 2048 + ks * 32));
            #pragma unroll
            for (int ni = 0; ni < 8; ni++)
                mma16(acc[ni], ah, &bb[ni >> 1][(ni & 1) * 2]);
        }
    }
}

// ---------------------------------------------------------------------------
// Persistent HMMA LSTM: 96 CTAs = 3 layers x 8 mtiles x 4 ntiles, 8 warps
// Weights SMEM-resident (loaded once); only acts streamed per step.
// ---------------------------------------------------------------------------
__global__ void __launch_bounds__(NT, 1)
lstm_tc(const float* __restrict__ W_ih1,
        const float* __restrict__ b_ih1, const float* __restrict__ b_hh1,
        const float* __restrict__ b_ih2, const float* __restrict__ b_hh2,
        const float* __restrict__ b_ih3, const float* __restrict__ b_hh3)
{
    extern __shared__ __align__(16) unsigned char smraw[];
    char* smp = (char*)(((uintptr_t)smraw + 1023) & ~(uintptr_t)1023);
    const uint32_t sb = s2u(smp);

    const int tid = threadIdx.x;
    const int w   = tid >> 5, l = tid & 31;
    const int layer = blockIdx.x >> 5;
    const int mt = (blockIdx.x & 31) >> 2;
    const int nt = blockIdx.x & 3;

    const int nm   = (layer == 0) ? 1 : 2;
    const int mi0  = (layer == 0) ? 0 : (layer == 1) ? 1 : 3;
    const int mi1  = (layer == 0) ? 0 : (layer == 1) ? 2 : 4;
    const int sl0  = (layer == 0) ? 0 : (layer == 1) ? 0 : 1;
    const int sl1  = (layer == 0) ? 0 : (layer == 1) ? 1 : 2;

    // fused bias + layer-1 input column (reordered rows)
    if (tid < 128) {
        const float* bi = (layer == 0) ? b_ih1 : (layer == 1) ? b_ih2 : b_ih3;
        const float* bh = (layer == 0) ? b_hh1 : (layer == 1) ? b_hh2 : b_hh3;
        int orow = (tid & 3) * 256 + mt * 32 + (tid >> 2);
        ((float*)(smp + SM_BIAS))[tid] = bi[orow] + bh[orow];
        ((float*)(smp + SM_W1))[tid]   = (layer == 0) ? W_ih1[orow] : 0.f;
    }

    // ---- load resident weights once (64KB per matrix) ----
    {
        const char* w0 = (const char*)&g_wb[mi0][mt][0];
        #pragma unroll
        for (int q = 0; q < 16; q++) {
            uint32_t o = (uint32_t)(q * 256 + tid) * 16;
            CPA(sb + SM_WRES + o, w0 + o);
        }
        if (nm == 2) {
            const char* w1 = (const char*)&g_wb[mi1][mt][0];
            #pragma unroll
            for (int q = 0; q < 16; q++) {
                uint32_t o = (uint32_t)(q * 256 + tid) * 16;
                CPA(sb + SM_WRES + 65536 + o, w1 + o);
            }
        }
        CPC();
        CPW(0);
    }
    __syncthreads();

    // ldmatrix lane base offsets: warp w owns A rows w*16..w*16+15
    const int a_off0 = (w * 16 + (l & 15)) * 128 + (l >> 4) * 16;
    const int b_off0 = ((l & 7) + ((l >> 4) & 1) * 8) * 128 + ((l >> 3) & 1) * 16;

    float cst[8];
    #pragma unroll
    for (int i = 0; i < 8; i++) cst[i] = 0.f;

    const int u = tid >> 3, n0 = (tid & 7) * 8;   // pointwise: unit u, 8 batches
    float* sD = (float*)(smp + SM_D);
    float* sH = (float*)(smp + SM_H);

    #pragma unroll 1
    for (int s = 0; s < TT + 2; s++) {
        const int rp = (s + 1) & 1, wp = s & 1;
        const int t = s - layer;
        if (t >= 0 && t < TT) {
            float acc[8][4];
            #pragma unroll
            for (int ni = 0; ni < 8; ni++)
                #pragma unroll
                for (int e = 0; e < 4; e++) acc[ni][e] = 0.f;

            // stage activations (both matrices), then compute against resident W
            stage_act(sb + SM_ACT, &g_ab[sl0][rp][nt][0], tid);
            CPC();
            if (nm == 2) {
                stage_act(sb + SM_ACT + ABUF_SZ, &g_ab[sl1][rp][nt][0], tid);
                CPC();
                CPW(1);
            } else {
                CPW(0);
            }
            __syncthreads();
            compute_mat(sb + SM_WRES, sb + SM_ACT, acc, a_off0, b_off0);
            if (nm == 2) {
                CPW(0);
                __syncthreads();
                compute_mat(sb + SM_WRES + 65536, sb + SM_ACT + ABUF_SZ,
                            acc, a_off0, b_off0);
            }
            __syncthreads();   // act reads done -> sD overlay safe

            // ---- store D frags to SMEM [128][68] (overlays act region) ----
            {
                const int row0 = w * 16 + (l >> 2);
                const int colb = (l & 3) * 2;
                #pragma unroll
                for (int ni = 0; ni < 8; ni++) {
                    float2* p0 = (float2*)&sD[row0 * 68 + ni * 8 + colb];
                    float2* p1 = (float2*)&sD[(row0 + 8) * 68 + ni * 8 + colb];
                    *p0 = make_float2(acc[ni][0], acc[ni][1]);
                    *p1 = make_float2(acc[ni][2], acc[ni][3]);
                }
            }
            __syncthreads();

            // ---- pointwise LSTM cell: thread = (unit u, batch octet n0) ----
            {
                const float* q0 = &sD[(4 * u + 0) * 68 + n0];
                const float* q1 = &sD[(4 * u + 1) * 68 + n0];
                const float* q2 = &sD[(4 * u + 2) * 68 + n0];
                const float* q3 = &sD[(4 * u + 3) * 68 + n0];
                const float b0 = ((float*)(smp + SM_BIAS))[4 * u + 0];
                const float b1 = ((float*)(smp + SM_BIAS))[4 * u + 1];
                const float b2 = ((float*)(smp + SM_BIAS))[4 * u + 2];
                const float b3 = ((float*)(smp + SM_BIAS))[4 * u + 3];
                float w0 = 0.f, w1 = 0.f, w2 = 0.f, w3 = 0.f;
                if (layer == 0) {
                    w0 = ((float*)(smp + SM_W1))[4 * u + 0];
                    w1 = ((float*)(smp + SM_W1))[4 * u + 1];
                    w2 = ((float*)(smp + SM_W1))[4 * u + 2];
                    w3 = ((float*)(smp + SM_W1))[4 * u + 3];
                }
                const int nb = nt * 64 + n0;
                float hloc[8];
                #pragma unroll
                for (int i = 0; i < 8; i++) {
                    float gi = q0[i] + b0, gf = q1[i] + b1;
                    float gg = q2[i] + b2, go = q3[i] + b3;
                    if (layer == 0) {
                        float xv = g_x[t][nb + i];
                        gi += w0 * xv; gf += w1 * xv; gg += w2 * xv; go += w3 * xv;
                    }
                    float I = sigf(gi), F = sigf(gf), G = tanhf(gg), O = sigf(go);
                    float cn = F * cst[i] + I * G;
                    cst[i] = cn;
                    hloc[i] = O * tanhf(cn);
                }
                if (layer == 2) {
                    float4* hp = (float4*)&g_hist[t][mt * 32 + u][nb];
                    hp[0] = make_float4(hloc[0], hloc[1], hloc[2], hloc[3]);
                    hp[1] = make_float4(hloc[4], hloc[5], hloc[6], hloc[7]);
                }
                #pragma unroll
                for (int i = 0; i < 8; i++)
                    sH[(n0 + i) * 33 + u] = hloc[i];
            }
            __syncthreads();

            // ---- transpose-write h as swizzled fp16 image ----
            {
                const int n = tid >> 2, q = tid & 3;   // n-row, unit-octet
                const float* hr = &sH[n * 33 + q * 8];
                uint32_t hw[4];
                #pragma unroll
                for (int e = 0; e < 4; e++) {
                    __half ah = __float2half_rn(hr[2 * e]);
                    __half bh2 = __float2half_rn(hr[2 * e + 1]);
                    hw[e] = (uint32_t)__half_as_ushort(ah)
                          | ((uint32_t)__half_as_ushort(bh2) << 16);
                }
                char* img = (char*)&g_ab[layer][wp][nt][(mt >> 1) * 4096];
                int off = n * 128 + (mt & 1) * 64 + q * 16;
                *(uint4*)(img + swz(off)) = make_uint4(hw[0], hw[1], hw[2], hw[3]);
            }
        }
        grid_sync((unsigned)(s + 1));
    }
}

// ---------------------------------------------------------------------------
// Output head
// ---------------------------------------------------------------------------
__global__ void __launch_bounds__(256)
linear_head(const float* __restrict__ W_lin, const float* __restrict__ b_lin,
            float* __restrict__ out)
{
    __shared__ float sw[HD];
    const int t = blockIdx.x, b = threadIdx.x;
    sw[b] = W_lin[b];
    __syncthreads();
    const float* hp = &g_hist[t][0][0];
    float s = 0.f;
    #pragma unroll 8
    for (int k = 0; k < HD; k++)
        s += hp[(size_t)k * BB + b] * sw[k];
    out[(size_t)b * TT + t] = s + b_lin[0];
}

// ---------------------------------------------------------------------------
// 4 graph nodes: init -> prep -> persistent -> head
// ---------------------------------------------------------------------------
extern "C" void kernel_launch(void* const* d_in, const int* in_sizes, int n_in,
                              void* d_out, int out_size)
{
    const float* input = (const float*)d_in[0];
    const float* W_ih1 = (const float*)d_in[1];
    const float* W_hh1 = (const float*)d_in[2];
    const float* b_ih1 = (const float*)d_in[3];
    const float* b_hh1 = (const float*)d_in[4];
    const float* W_ih2 = (const float*)d_in[5];
    const float* W_hh2 = (const float*)d_in[6];
    const float* b_ih2 = (const float*)d_in[7];
    const float* b_hh2 = (const float*)d_in[8];
    const float* W_ih3 = (const float*)d_in[9];
    const float* W_hh3 = (const float*)d_in[10];
    const float* b_ih3 = (const float*)d_in[11];
    const float* b_hh3 = (const float*)d_in[12];
    const float* W_lin = (const float*)d_in[13];
    const float* b_lin = (const float*)d_in[14];
    float* out = (float*)d_out;

    cudaFuncSetAttribute(lstm_tc, cudaFuncAttributeMaxDynamicSharedMemorySize, SM_BYTES);

    init_state<<<256, 256>>>(input);
    prep_weights<<<512, 256>>>(W_hh1, W_ih2, W_hh2, W_ih3, W_hh3);
    lstm_tc<<<NB, NT, SM_BYTES>>>(W_ih1, b_ih1, b_hh1, b_ih2, b_hh2, b_ih3, b_hh3);
    linear_head<<<TT, 256>>>(W_lin, b_lin, out);
}